// round 10
// baseline (speedup 1.0000x reference)
#include <cuda_runtime.h>
#include <cuda_bf16.h>

#define NN 1024
#define HID 256
#define NH 8
#define HD 32
#define NE 16384

#define TBL_N 8192
#define TBL_MAX 24.0f
#define TBL_SCALE ((float)(TBL_N - 1) / TBL_MAX)

typedef unsigned long long ull;

// ---- packed fp32x2 helpers (sm_103a FFMA2) ----------------------------------
__device__ __forceinline__ ull pack2(float lo, float hi) {
    ull r; asm("mov.b64 %0, {%1, %2};" : "=l"(r) : "f"(lo), "f"(hi)); return r;
}
__device__ __forceinline__ float2 unpack2(ull v) {
    float2 f; asm("mov.b64 {%0, %1}, %2;" : "=f"(f.x), "=f"(f.y) : "l"(v)); return f;
}
__device__ __forceinline__ void fma2(ull& d, ull a, ull b) {
    asm("fma.rn.f32x2 %0, %1, %2, %0;" : "+l"(d) : "l"(a), "l"(b));
}

// ---------------- scratch (static device memory; no allocations) -------------
__device__ float    g_q[NN * HID];
__device__ float    g_k[NN * HID];
__device__ float    g_v[NN * HID];
__device__ float    g_gateh[NN * 4 * HID];
__device__ float    g_gate[NN * 2];
__device__ unsigned g_adj[NN * 32];
__device__ unsigned g_pa[NN * 32];
__device__ unsigned g_pb[NN * 32];
__device__ float    g_ttab[16];                  // [path_val(0/1)][head]
__device__ float    g_tbl[TBL_N * 8];            // geo MLP lookup table [i][h]
__device__ float    g_logits[NN * NH * NN];      // 32 MB, [n][h][m], raw logits
__device__ float2   g_stats[NN * NH];            // per-row (max, 1/sum)
__device__ float    g_attnout[NN * HID];
__device__ float    g_proj[NN * HID];

// ------- setup: geo table (blocks 0-31) + zero adj slices + ttab (block 32) --
__global__ void setup_kernel(const float* __restrict__ gw1, const float* __restrict__ gb1,
                             const float* __restrict__ gw2, const float* __restrict__ gb2,
                             const float* __restrict__ tw1, const float* __restrict__ tb1,
                             const float* __restrict__ tw2, const float* __restrict__ tb2) {
    int b = blockIdx.x, tid = threadIdx.x;
    if (b < 32) {
#pragma unroll
        for (int t = 0; t < 4; t++) g_adj[b * 1024 + tid + 256 * t] = 0u;
        int i = b * 256 + tid;
        float dist = (float)i * (TBL_MAX / (float)(TBL_N - 1));
        float a[8];
#pragma unroll
        for (int h = 0; h < 8; h++) a[h] = gb2[h];
        for (int c = 0; c < 32; c++) {
            float hv = fmaf(dist, gw1[c], gb1[c]);
            float s = __fdividef(hv, 1.f + __expf(-hv));
#pragma unroll
            for (int h = 0; h < 8; h++) a[h] = fmaf(s, gw2[c * 8 + h], a[h]);
        }
#pragma unroll
        for (int h = 0; h < 8; h++) g_tbl[i * 8 + h] = a[h];
    } else {
        if (tid < 16) {
            float pv = (float)(tid >> 3);
            int h = tid & 7;
            float acc = tb2[h];
            for (int c = 0; c < 32; c++) {
                float hv = fmaf(pv, tw1[c], tb1[c]);
                float s = __fdividef(hv, 1.f + __expf(-hv));
                acc = fmaf(s, tw2[c * 8 + h], acc);
            }
            g_ttab[tid] = acc;
        }
    }
}

// ---------------- scatter edges with inline dtype detect ----------------------
__global__ void scatter_edges_kernel(const unsigned* __restrict__ w) {
    bool is64 = true;
#pragma unroll
    for (int i = 1; i < 16; i += 2) is64 &= (w[i] == 0u);
    int e = blockIdx.x * blockDim.x + threadIdx.x;
    if (e >= NE) return;
    int s, d;
    if (is64) {
        const long long* p = (const long long*)w;
        s = (int)p[e];
        d = (int)p[NE + e];
    } else {
        const int* p = (const int*)w;
        s = p[e];
        d = p[NE + e];
    }
    atomicOr(&g_adj[s * 32 + (d >> 5)], 1u << (d & 31));
}

// path = min(path, path @ adj): binary reachability step on bitsets.
#define LIST_CAP 512
__global__ __launch_bounds__(256) void path_round_kernel(int r) {
    const unsigned* in = (r == 0) ? g_adj : ((r == 1) ? g_pa : g_pb);
    unsigned* out = (r == 1) ? g_pb : g_pa;
    __shared__ unsigned short lists[8][LIST_CAP];
    int warp = threadIdx.x >> 5, lane = threadIdx.x & 31;
    int row = blockIdx.x * 8 + warp;
    unsigned w = in[row * 32 + lane];
    int c = __popc(w);
    int pre = c;
#pragma unroll
    for (int o = 1; o < 32; o <<= 1) {
        int x = __shfl_up_sync(~0u, pre, o);
        if (lane >= o) pre += x;
    }
    int total = __shfl_sync(~0u, pre, 31);
    unsigned acc = 0u;
    if (total <= LIST_CAP) {
        int k = pre - c;
        unsigned tmp = w;
        while (tmp) {
            int b = __ffs(tmp) - 1; tmp &= tmp - 1;
            lists[warp][k++] = (unsigned short)(lane * 32 + b);
        }
        __syncwarp();
        int j = 0;
        for (; j + 8 <= total; j += 8) {
            unsigned a0 = g_adj[lists[warp][j + 0] * 32 + lane];
            unsigned a1 = g_adj[lists[warp][j + 1] * 32 + lane];
            unsigned a2 = g_adj[lists[warp][j + 2] * 32 + lane];
            unsigned a3 = g_adj[lists[warp][j + 3] * 32 + lane];
            unsigned a4 = g_adj[lists[warp][j + 4] * 32 + lane];
            unsigned a5 = g_adj[lists[warp][j + 5] * 32 + lane];
            unsigned a6 = g_adj[lists[warp][j + 6] * 32 + lane];
            unsigned a7 = g_adj[lists[warp][j + 7] * 32 + lane];
            acc |= (a0 | a1) | (a2 | a3) | (a4 | a5) | (a6 | a7);
        }
        for (; j < total; j++) acc |= g_adj[lists[warp][j] * 32 + lane];
    } else {
        for (int ww = 0; ww < 32; ww++) {
            unsigned word = __shfl_sync(~0u, w, ww);
            while (word) {
                int b = __ffs(word) - 1; word &= word - 1;
                acc |= g_adj[(ww * 32 + b) * 32 + lane];
            }
        }
    }
    out[row * 32 + lane] = w & acc;
}

// -------- 64x128 tiled SGEMM, 128 thr, 8x8 microtile, FFMA2 ------------------
// C = [A0|A1] @ B + bias [, silu].  Thread grid 8 rows x 16 cols.
__device__ __forceinline__ void gemm_body(
    const float* __restrict__ A0, const float* __restrict__ A1, int ksplit,
    int lda, const float* __restrict__ B, int ldb,
    const float* __restrict__ bias, float* __restrict__ C, int ldc, int K, int act)
{
    __shared__ float As[16][68];     // [k][row] 64 rows + pad
    __shared__ float Bs[16][128];    // [k][col]
    int tid = threadIdx.x;
    int tr = tid >> 4, tc = tid & 15;
    int row0 = blockIdx.y * 64, col0 = blockIdx.x * 128;

    ull acc2[4][8];                  // row pairs (tr*8+2i, +1) x cols tc*8+j
#pragma unroll
    for (int i = 0; i < 4; i++)
#pragma unroll
        for (int j = 0; j < 8; j++) acc2[i][j] = 0ull;

    int ar = tid >> 1, kq = (tid & 1) << 3;   // A: 64 rows x two 8-wide k slabs
    int bk = tid >> 3, bn = (tid & 7) << 4;   // B: 16 k-rows x 128 cols

    for (int k0 = 0; k0 < K; k0 += 16) {
        const float* Ap = (k0 < ksplit)
            ? &A0[(row0 + ar) * lda + k0 + kq]
            : &A1[(row0 + ar) * lda + (k0 - ksplit) + kq];
        float4 a0 = *(const float4*)Ap;
        float4 a1 = *(const float4*)(Ap + 4);
        As[kq + 0][ar] = a0.x; As[kq + 1][ar] = a0.y;
        As[kq + 2][ar] = a0.z; As[kq + 3][ar] = a0.w;
        As[kq + 4][ar] = a1.x; As[kq + 5][ar] = a1.y;
        As[kq + 6][ar] = a1.z; As[kq + 7][ar] = a1.w;
        const float* Bp = &B[(k0 + bk) * ldb + col0 + bn];
#pragma unroll
        for (int i = 0; i < 4; i++)
            *(float4*)&Bs[bk][bn + 4 * i] = *(const float4*)(Bp + 4 * i);
        __syncthreads();
#pragma unroll
        for (int kk = 0; kk < 16; kk++) {
            ulonglong2 aA = *(const ulonglong2*)&As[kk][tr * 8];
            ulonglong2 aB = *(const ulonglong2*)&As[kk][tr * 8 + 4];
            float4 b0 = *(const float4*)&Bs[kk][tc * 8];
            float4 b1 = *(const float4*)&Bs[kk][tc * 8 + 4];
            ull bb[8];
            bb[0] = pack2(b0.x, b0.x); bb[1] = pack2(b0.y, b0.y);
            bb[2] = pack2(b0.z, b0.z); bb[3] = pack2(b0.w, b0.w);
            bb[4] = pack2(b1.x, b1.x); bb[5] = pack2(b1.y, b1.y);
            bb[6] = pack2(b1.z, b1.z); bb[7] = pack2(b1.w, b1.w);
#pragma unroll
            for (int j = 0; j < 8; j++) {
                fma2(acc2[0][j], aA.x, bb[j]);
                fma2(acc2[1][j], aA.y, bb[j]);
                fma2(acc2[2][j], aB.x, bb[j]);
                fma2(acc2[3][j], aB.y, bb[j]);
            }
        }
        __syncthreads();
    }

#pragma unroll
    for (int i = 0; i < 4; i++) {
        int r = row0 + tr * 8 + 2 * i;
        float vlo[8], vhi[8];
#pragma unroll
        for (int j = 0; j < 8; j++) {
            float2 v = unpack2(acc2[i][j]);
            float bs = bias[col0 + tc * 8 + j];
            vlo[j] = v.x + bs;
            vhi[j] = v.y + bs;
            if (act) {
                vlo[j] = __fdividef(vlo[j], 1.f + __expf(-vlo[j]));
                vhi[j] = __fdividef(vhi[j], 1.f + __expf(-vhi[j]));
            }
        }
        float* Crow0 = &C[r * ldc + col0 + tc * 8];
        float* Crow1 = &C[(r + 1) * ldc + col0 + tc * 8];
        *(float4*)(Crow0 + 0) = make_float4(vlo[0], vlo[1], vlo[2], vlo[3]);
        *(float4*)(Crow0 + 4) = make_float4(vlo[4], vlo[5], vlo[6], vlo[7]);
        *(float4*)(Crow1 + 0) = make_float4(vhi[0], vhi[1], vhi[2], vhi[3]);
        *(float4*)(Crow1 + 4) = make_float4(vhi[4], vhi[5], vhi[6], vhi[7]);
    }
}

__global__ __launch_bounds__(128) void sgemm_wide(
    const float* __restrict__ A0, const float* __restrict__ A1, int ksplit,
    int lda, const float* __restrict__ B, int ldb,
    const float* __restrict__ bias, float* __restrict__ C, int ldc, int K, int act)
{
    gemm_body(A0, A1, ksplit, lda, B, ldb, bias, C, ldc, K, act);
}

// q/k/v projections fused via blockIdx.z
__global__ __launch_bounds__(128) void qkv_kernel(
    const float* __restrict__ src, const float* __restrict__ tgt,
    const float* __restrict__ Wq, const float* __restrict__ bq,
    const float* __restrict__ Wk, const float* __restrict__ bk,
    const float* __restrict__ Wv, const float* __restrict__ bv)
{
    int z = blockIdx.z;
    const float* A = (z == 0) ? src : tgt;
    const float* W = (z == 0) ? Wq : ((z == 1) ? Wk : Wv);
    const float* b = (z == 0) ? bq : ((z == 1) ? bk : bv);
    float* C = (z == 0) ? g_q : ((z == 1) ? g_k : g_v);
    gemm_body(A, A, 256, 256, W, 256, b, C, 256, 256, 0);
}

// gate logits: 2 dots of length 1024 per node, then 2-way softmax
__global__ __launch_bounds__(256) void gate2_kernel(const float* __restrict__ w2,
                                                    const float* __restrict__ b2) {
    int n = blockIdx.x, tid = threadIdx.x;
    const float* hrow = g_gateh + n * 1024;
    float s0 = 0.f, s1 = 0.f;
#pragma unroll
    for (int t = 0; t < 4; t++) {
        int j = tid + 256 * t;
        float hv = hrow[j];
        s0 = fmaf(hv, w2[j * 2 + 0], s0);
        s1 = fmaf(hv, w2[j * 2 + 1], s1);
    }
    for (int o = 16; o; o >>= 1) {
        s0 += __shfl_xor_sync(~0u, s0, o);
        s1 += __shfl_xor_sync(~0u, s1, o);
    }
    __shared__ float r0[8], r1[8];
    if ((tid & 31) == 0) { r0[tid >> 5] = s0; r1[tid >> 5] = s1; }
    __syncthreads();
    if (tid == 0) {
        float l0 = b2[0], l1 = b2[1];
        for (int j = 0; j < 8; j++) { l0 += r0[j]; l1 += r1[j]; }
        float m = fmaxf(l0, l1);
        float e0 = __expf(l0 - m), e1 = __expf(l1 - m);
        float inv = __fdividef(1.f, e0 + e1);
        g_gate[n * 2 + 0] = e0 * inv;
        g_gate[n * 2 + 1] = e1 * inv;
    }
}

// ---------------- fused logits: QK/sqrt(D) + gate0*geoTbl(dist) + gate1*topo -
#define QPAD 260
#define LOGITS_SMEM ((64 * QPAD + 320) * 4)

__global__ __launch_bounds__(256) void logits_kernel(const float* __restrict__ pos)
{
    extern __shared__ float sh[];
    float* qs  = sh;                       // 32 x 260
    float* ks  = sh + 32 * QPAD;           // 32 x 260
    float* ext = sh + 64 * QPAD;
    float* sg0 = ext;                      // 32
    float* sg1 = sg0 + 32;                 // 32
    float* spn = sg1 + 32;                 // 32*3
    float* spm = spn + 96;                 // 32*3
    float* stt = spm + 96;                 // 16
    unsigned* spw = (unsigned*)(stt + 16); // 32

    int tid = threadIdx.x;
    int m0 = blockIdx.x * 32, n0 = blockIdx.y * 32;

#pragma unroll
    for (int t = 0; t < 8; t++) {
        int lin = tid + 256 * t;
        int r = lin >> 6, c4 = (lin & 63) << 2;
        *(float4*)&qs[r * QPAD + c4] = *(const float4*)&g_q[(n0 + r) * 256 + c4];
        *(float4*)&ks[r * QPAD + c4] = *(const float4*)&g_k[(m0 + r) * 256 + c4];
    }
    if (tid < 32) {
        sg0[tid] = g_gate[(n0 + tid) * 2 + 0];
        sg1[tid] = g_gate[(n0 + tid) * 2 + 1];
        spw[tid] = g_pa[(n0 + tid) * 32 + blockIdx.x];
        spn[tid * 3 + 0] = pos[(n0 + tid) * 3 + 0];
        spn[tid * 3 + 1] = pos[(n0 + tid) * 3 + 1];
        spn[tid * 3 + 2] = pos[(n0 + tid) * 3 + 2];
        spm[tid * 3 + 0] = pos[(m0 + tid) * 3 + 0];
        spm[tid * 3 + 1] = pos[(m0 + tid) * 3 + 1];
        spm[tid * 3 + 2] = pos[(m0 + tid) * 3 + 2];
    }
    if (tid < 16) stt[tid] = g_ttab[tid];
    __syncthreads();

    int mi = tid & 31, nbase = tid >> 5;
    float res[4][8];
    float px = spm[mi * 3 + 0], py = spm[mi * 3 + 1], pz = spm[mi * 3 + 2];

#pragma unroll
    for (int i = 0; i < 4; i++) {
        int ni = nbase + 8 * i;
        float dx = spn[ni * 3 + 0] - px;
        float dy = spn[ni * 3 + 1] - py;
        float dz = spn[ni * 3 + 2] - pz;
        float dist = sqrtf(fmaxf(dx * dx + dy * dy + dz * dz, 1e-12f));
        float gv0 = sg0[ni], gv1 = sg1[ni];
        int bit = (spw[ni] >> mi) & 1;

        float t = fminf(dist, TBL_MAX) * TBL_SCALE;
        int i0 = (int)t;
        if (i0 > TBL_N - 2) i0 = TBL_N - 2;
        float fr = t - (float)i0;
        const float4* tb = (const float4*)&g_tbl[i0 * 8];
        float4 r0 = __ldg(tb + 0), r1 = __ldg(tb + 1);
        float4 r2 = __ldg(tb + 2), r3 = __ldg(tb + 3);
        float a[8];
        a[0] = r0.x + fr * (r2.x - r0.x); a[1] = r0.y + fr * (r2.y - r0.y);
        a[2] = r0.z + fr * (r2.z - r0.z); a[3] = r0.w + fr * (r2.w - r0.w);
        a[4] = r1.x + fr * (r3.x - r1.x); a[5] = r1.y + fr * (r3.y - r1.y);
        a[6] = r1.z + fr * (r3.z - r1.z); a[7] = r1.w + fr * (r3.w - r1.w);
#pragma unroll
        for (int h = 0; h < 8; h++)
            res[i][h] = gv0 * a[h] + gv1 * stt[bit * 8 + h];
    }

    const float scale = 0.17677669529663687f;   // 1/sqrt(32)
#pragma unroll
    for (int h = 0; h < 8; h++) {
        float4 kr[8];
#pragma unroll
        for (int j = 0; j < 8; j++)
            kr[j] = *(const float4*)&ks[mi * QPAD + h * 32 + j * 4];
#pragma unroll
        for (int i = 0; i < 4; i++) {
            int ni = nbase + 8 * i;
            float s = 0.f;
#pragma unroll
            for (int j = 0; j < 8; j++) {
                float4 qv = *(const float4*)&qs[ni * QPAD + h * 32 + j * 4];
                s += qv.x * kr[j].x + qv.y * kr[j].y + qv.z * kr[j].z + qv.w * kr[j].w;
            }
            res[i][h] = fmaf(s, scale, res[i][h]);
        }
    }

#pragma unroll
    for (int i = 0; i < 4; i++) {
        int ng = n0 + nbase + 8 * i;
#pragma unroll
        for (int h = 0; h < 8; h++)
            g_logits[(ng * 8 + h) * 1024 + m0 + mi] = res[i][h];
    }
}

// ---------------- row stats (max, 1/sum of exp) -------------------------------
__global__ __launch_bounds__(256) void stats_kernel() {
    int row = blockIdx.x;
    const float* p = g_logits + (long)row * 1024;
    int tid = threadIdx.x;
    float4 v = *(const float4*)&p[tid * 4];
    float mx = fmaxf(fmaxf(v.x, v.y), fmaxf(v.z, v.w));
    for (int o = 16; o; o >>= 1) mx = fmaxf(mx, __shfl_xor_sync(~0u, mx, o));
    __shared__ float rm[8], rs[8];
    if ((tid & 31) == 0) rm[tid >> 5] = mx;
    __syncthreads();
    mx = rm[0];
#pragma unroll
    for (int j = 1; j < 8; j++) mx = fmaxf(mx, rm[j]);
    float s = __expf(v.x - mx) + __expf(v.y - mx) + __expf(v.z - mx) + __expf(v.w - mx);
    for (int o = 16; o; o >>= 1) s += __shfl_xor_sync(~0u, s, o);
    if ((tid & 31) == 0) rs[tid >> 5] = s;
    __syncthreads();
    if (tid == 0) {
        float tot = 0.f;
#pragma unroll
        for (int j = 0; j < 8; j++) tot += rs[j];
        g_stats[row] = make_float2(mx, __fdividef(1.f, tot));
    }
}

// -------- PV with inline softmax: out[n,h*32+d] = sum_m p[n,h,m] v[m,h*32+d] -
__global__ __launch_bounds__(256) void pv_kernel() {
    int h = blockIdx.x, n0 = blockIdx.y * 64;
    __shared__ float As[64][36];   // n x m (softmaxed probs)
    __shared__ float Bs[32][32];   // m x d
    __shared__ float2 sstat[64];
    int tid = threadIdx.x;
    int dxi = tid & 31;
    int ty = tid >> 5;
    if (tid < 64) sstat[tid] = g_stats[(n0 + tid) * 8 + h];
    __syncthreads();
    float acc[8];
#pragma unroll
    for (int i = 0; i < 8; i++) acc[i] = 0.f;

    for (int m0 = 0; m0 < 1024; m0 += 32) {
#pragma unroll
        for (int t = 0; t < 2; t++) {
            int lin = tid + 256 * t;
            int r = lin >> 3, c4 = (lin & 7) << 2;
            float4 v = *(const float4*)&g_logits[((long)(n0 + r) * 8 + h) * 1024 + m0 + c4];
            float2 st = sstat[r];
            v.x = __expf(v.x - st.x) * st.y;
            v.y = __expf(v.y - st.x) * st.y;
            v.z = __expf(v.z - st.x) * st.y;
            v.w = __expf(v.w - st.x) * st.y;
            *(float4*)&As[r][c4] = v;
        }
        {
            int r = tid >> 3, c4 = (tid & 7) << 2;
            *(float4*)&Bs[r][c4] = *(const float4*)&g_v[(m0 + r) * 256 + h * 32 + c4];
        }
        __syncthreads();
#pragma unroll
        for (int mm = 0; mm < 32; mm += 4) {
            float b0 = Bs[mm + 0][dxi], b1 = Bs[mm + 1][dxi];
            float b2 = Bs[mm + 2][dxi], b3 = Bs[mm + 3][dxi];
#pragma unroll
            for (int i = 0; i < 8; i++) {
                float4 a = *(const float4*)&As[ty + 8 * i][mm];
                acc[i] = fmaf(a.x, b0, fmaf(a.y, b1, fmaf(a.z, b2, fmaf(a.w, b3, acc[i]))));
            }
        }
        __syncthreads();
    }
#pragma unroll
    for (int i = 0; i < 8; i++)
        g_attnout[(n0 + ty + 8 * i) * 256 + h * 32 + dxi] = acc[i];
}

// ---------------- residual + layernorm ----------------------------------------
__global__ __launch_bounds__(256) void ln_kernel(const float* __restrict__ src,
                                                 const float* __restrict__ g,
                                                 const float* __restrict__ b,
                                                 float* __restrict__ out) {
    int n = blockIdx.x, tid = threadIdx.x;
    float x = src[n * 256 + tid] + g_proj[n * 256 + tid];
    float s = x;
    for (int o = 16; o; o >>= 1) s += __shfl_xor_sync(~0u, s, o);
    __shared__ float r1[8], r2[8];
    if ((tid & 31) == 0) r1[tid >> 5] = s;
    __syncthreads();
    float tot = 0.f;
#pragma unroll
    for (int j = 0; j < 8; j++) tot += r1[j];
    float mu = tot * (1.f / 256.f);
    float d = x - mu;
    float s2 = d * d;
    for (int o = 16; o; o >>= 1) s2 += __shfl_xor_sync(~0u, s2, o);
    if ((tid & 31) == 0) r2[tid >> 5] = s2;
    __syncthreads();
    float var = 0.f;
#pragma unroll
    for (int j = 0; j < 8; j++) var += r2[j];
    var *= (1.f / 256.f);
    out[n * 256 + tid] = d * rsqrtf(var + 1e-5f) * g[tid] + b[tid];
}

// ---------------- launch ------------------------------------------------------
extern "C" void kernel_launch(void* const* d_in, const int* in_sizes, int n_in,
                              void* d_out, int out_size) {
    const float* src_feat = (const float*)d_in[0];
    const float* tgt_feat = (const float*)d_in[1];
    const float* src_pos  = (const float*)d_in[2];
    const void*  edges    = d_in[3];
    const float* Wq = (const float*)d_in[4],  *bq = (const float*)d_in[5];
    const float* Wk = (const float*)d_in[6],  *bk = (const float*)d_in[7];
    const float* Wv = (const float*)d_in[8],  *bv = (const float*)d_in[9];
    const float* geo_w1 = (const float*)d_in[10], *geo_b1 = (const float*)d_in[11];
    const float* geo_w2 = (const float*)d_in[12], *geo_b2 = (const float*)d_in[13];
    const float* top_w1 = (const float*)d_in[14], *top_b1 = (const float*)d_in[15];
    const float* top_w2 = (const float*)d_in[16], *top_b2 = (const float*)d_in[17];
    const float* gate_w1 = (const float*)d_in[18], *gate_b1 = (const float*)d_in[19];
    const float* gate_w2 = (const float*)d_in[20], *gate_b2 = (const float*)d_in[21];
    const float* Wo = (const float*)d_in[22], *bo = (const float*)d_in[23];
    const float* ln_g = (const float*)d_in[24], *ln_b = (const float*)d_in[25];
    float* out = (float*)d_out;

    void *pgateh, *pattn, *pproj;
    cudaGetSymbolAddress(&pgateh, g_gateh);
    cudaGetSymbolAddress(&pattn, g_attnout);
    cudaGetSymbolAddress(&pproj, g_proj);

    cudaFuncSetAttribute(logits_kernel,
                         cudaFuncAttributeMaxDynamicSharedMemorySize, LOGITS_SMEM);

    // 1: geo table + zero adj + ttab (fused setup)
    setup_kernel<<<33, 256>>>(geo_w1, geo_b1, geo_w2, geo_b2,
                              top_w1, top_b1, top_w2, top_b2);
    // 2: scatter edges (inline dtype detect)
    scatter_edges_kernel<<<64, 256>>>((const unsigned*)edges);
    // 3: path round 1
    path_round_kernel<<<128, 256>>>(0);
    // 4: gate MLP GEMM (positioned for ncu capture): 1024x1024, K=512
    sgemm_wide<<<dim3(8, 16), 128>>>(src_feat, tgt_feat, 256, 256, gate_w1, 1024,
                                     gate_b1, (float*)pgateh, 1024, 512, 1);
    // 5-6: path rounds 2,3 (final path in g_pa)
    path_round_kernel<<<128, 256>>>(1);
    path_round_kernel<<<128, 256>>>(2);
    // 7: q/k/v projections: 1024x256 each, 96 blocks
    qkv_kernel<<<dim3(2, 16, 3), 128>>>(src_feat, tgt_feat, Wq, bq, Wk, bk, Wv, bv);
    // 8: gate head + 2-way softmax
    gate2_kernel<<<1024, 256>>>(gate_w2, gate_b2);
    // 9-11: fused logits, row stats, PV
    logits_kernel<<<dim3(32, 32), 256, LOGITS_SMEM>>>(src_pos);
    stats_kernel<<<8192, 256>>>();
    pv_kernel<<<dim3(8, 16), 256>>>();
    // 12: output projection: 1024x256
    sgemm_wide<<<dim3(2, 16), 128>>>((const float*)pattn, (const float*)pattn, 256, 256,
                                     Wo, 256, bo, (float*)pproj, 256, 256, 0);
    // 13: residual + layernorm
    ln_kernel<<<1024, 256>>>(src_feat, ln_g, ln_b, out);
}

// round 11
// speedup vs baseline: 1.0658x; 1.0658x over previous
#include <cuda_runtime.h>
#include <cuda_bf16.h>

#define NN 1024
#define HID 256
#define NH 8
#define HD 32
#define NE 16384

#define TBL_N 8192
#define TBL_MAX 24.0f
#define TBL_SCALE ((float)(TBL_N - 1) / TBL_MAX)

typedef unsigned long long ull;

// ---- packed fp32x2 helpers (sm_103a FFMA2) ----------------------------------
__device__ __forceinline__ ull pack2(float lo, float hi) {
    ull r; asm("mov.b64 %0, {%1, %2};" : "=l"(r) : "f"(lo), "f"(hi)); return r;
}
__device__ __forceinline__ float2 unpack2(ull v) {
    float2 f; asm("mov.b64 {%0, %1}, %2;" : "=f"(f.x), "=f"(f.y) : "l"(v)); return f;
}
__device__ __forceinline__ void fma2(ull& d, ull a, ull b) {
    asm("fma.rn.f32x2 %0, %1, %2, %0;" : "+l"(d) : "l"(a), "l"(b));
}

// ---------------- scratch (static device memory; no allocations) -------------
__device__ float    g_q[NN * HID];
__device__ float    g_k[NN * HID];
__device__ float    g_v[NN * HID];
__device__ float    g_gateh[NN * 4 * HID];
__device__ float    g_gate[NN * 2];
__device__ unsigned g_adj[NN * 32];
__device__ unsigned g_pa[NN * 32];
__device__ unsigned g_pb[NN * 32];
__device__ float    g_ttab[16];                  // [path_val(0/1)][head]
__device__ float    g_tbl[TBL_N * 8];            // geo MLP lookup table [i][h]
__device__ float    g_logits[NN * NH * NN];      // 32 MB, [n][h][m], raw logits
__device__ float2   g_stats[NN * NH];            // per-row (max, 1/sum)
__device__ float    g_attnout[NN * HID];
__device__ float    g_proj[NN * HID];

// ------- setup: geo table (blocks 0-31) + zero adj slices + ttab (block 32) --
__global__ void setup_kernel(const float* __restrict__ gw1, const float* __restrict__ gb1,
                             const float* __restrict__ gw2, const float* __restrict__ gb2,
                             const float* __restrict__ tw1, const float* __restrict__ tb1,
                             const float* __restrict__ tw2, const float* __restrict__ tb2) {
    int b = blockIdx.x, tid = threadIdx.x;
    if (b < 32) {
#pragma unroll
        for (int t = 0; t < 4; t++) g_adj[b * 1024 + tid + 256 * t] = 0u;
        int i = b * 256 + tid;
        float dist = (float)i * (TBL_MAX / (float)(TBL_N - 1));
        float a[8];
#pragma unroll
        for (int h = 0; h < 8; h++) a[h] = gb2[h];
        for (int c = 0; c < 32; c++) {
            float hv = fmaf(dist, gw1[c], gb1[c]);
            float s = __fdividef(hv, 1.f + __expf(-hv));
#pragma unroll
            for (int h = 0; h < 8; h++) a[h] = fmaf(s, gw2[c * 8 + h], a[h]);
        }
#pragma unroll
        for (int h = 0; h < 8; h++) g_tbl[i * 8 + h] = a[h];
    } else {
        if (tid < 16) {
            float pv = (float)(tid >> 3);
            int h = tid & 7;
            float acc = tb2[h];
            for (int c = 0; c < 32; c++) {
                float hv = fmaf(pv, tw1[c], tb1[c]);
                float s = __fdividef(hv, 1.f + __expf(-hv));
                acc = fmaf(s, tw2[c * 8 + h], acc);
            }
            g_ttab[tid] = acc;
        }
    }
}

// ---------------- scatter edges with inline dtype detect ----------------------
__global__ void scatter_edges_kernel(const unsigned* __restrict__ w) {
    bool is64 = true;
#pragma unroll
    for (int i = 1; i < 16; i += 2) is64 &= (w[i] == 0u);
    int e = blockIdx.x * blockDim.x + threadIdx.x;
    if (e >= NE) return;
    int s, d;
    if (is64) {
        const long long* p = (const long long*)w;
        s = (int)p[e];
        d = (int)p[NE + e];
    } else {
        const int* p = (const int*)w;
        s = p[e];
        d = p[NE + e];
    }
    atomicOr(&g_adj[s * 32 + (d >> 5)], 1u << (d & 31));
}

// path = min(path, path @ adj): binary reachability step on bitsets.
#define LIST_CAP 512
__global__ __launch_bounds__(256) void path_round_kernel(int r) {
    const unsigned* in = (r == 0) ? g_adj : ((r == 1) ? g_pa : g_pb);
    unsigned* out = (r == 1) ? g_pb : g_pa;
    __shared__ unsigned short lists[8][LIST_CAP];
    int warp = threadIdx.x >> 5, lane = threadIdx.x & 31;
    int row = blockIdx.x * 8 + warp;
    unsigned w = in[row * 32 + lane];
    int c = __popc(w);
    int pre = c;
#pragma unroll
    for (int o = 1; o < 32; o <<= 1) {
        int x = __shfl_up_sync(~0u, pre, o);
        if (lane >= o) pre += x;
    }
    int total = __shfl_sync(~0u, pre, 31);
    unsigned acc = 0u;
    if (total <= LIST_CAP) {
        int k = pre - c;
        unsigned tmp = w;
        while (tmp) {
            int b = __ffs(tmp) - 1; tmp &= tmp - 1;
            lists[warp][k++] = (unsigned short)(lane * 32 + b);
        }
        __syncwarp();
        int j = 0;
        for (; j + 8 <= total; j += 8) {
            unsigned a0 = g_adj[lists[warp][j + 0] * 32 + lane];
            unsigned a1 = g_adj[lists[warp][j + 1] * 32 + lane];
            unsigned a2 = g_adj[lists[warp][j + 2] * 32 + lane];
            unsigned a3 = g_adj[lists[warp][j + 3] * 32 + lane];
            unsigned a4 = g_adj[lists[warp][j + 4] * 32 + lane];
            unsigned a5 = g_adj[lists[warp][j + 5] * 32 + lane];
            unsigned a6 = g_adj[lists[warp][j + 6] * 32 + lane];
            unsigned a7 = g_adj[lists[warp][j + 7] * 32 + lane];
            acc |= (a0 | a1) | (a2 | a3) | (a4 | a5) | (a6 | a7);
        }
        for (; j < total; j++) acc |= g_adj[lists[warp][j] * 32 + lane];
    } else {
        for (int ww = 0; ww < 32; ww++) {
            unsigned word = __shfl_sync(~0u, w, ww);
            while (word) {
                int b = __ffs(word) - 1; word &= word - 1;
                acc |= g_adj[(ww * 32 + b) * 32 + lane];
            }
        }
    }
    out[row * 32 + lane] = w & acc;
}

// -------- 128x64 tiled SGEMM body, 256 thr, 8x4 microtile, FFMA2 -------------
// C = [A0|A1] @ B + bias [, silu].  (R7-verified body)
__device__ __forceinline__ void gemm_body(
    const float* __restrict__ A0, const float* __restrict__ A1, int ksplit,
    int lda, const float* __restrict__ B, int ldb,
    const float* __restrict__ bias, float* __restrict__ C, int ldc, int K, int act)
{
    __shared__ float As[16][132];   // [k][row], 128 rows + pad
    __shared__ float Bs[16][64];
    int tid = threadIdx.x;
    int tx = tid & 15, ty = tid >> 4;
    int row0 = blockIdx.y * 128, col0 = blockIdx.x * 64;
    ull acc2[4][4];                  // row pairs (ty*8+2*i2, +1) x cols tx*4+j
#pragma unroll
    for (int i = 0; i < 4; i++)
#pragma unroll
        for (int j = 0; j < 4; j++) acc2[i][j] = 0ull;

    int ar = tid >> 1, acq = (tid & 1) << 3;
    int bk = tid >> 4, bn = (tid & 15) << 2;

    for (int k0 = 0; k0 < K; k0 += 16) {
        const float* Ap = (k0 < ksplit)
            ? &A0[(row0 + ar) * lda + k0 + acq]
            : &A1[(row0 + ar) * lda + (k0 - ksplit) + acq];
        float4 av0 = *(const float4*)Ap;
        float4 av1 = *(const float4*)(Ap + 4);
        As[acq + 0][ar] = av0.x; As[acq + 1][ar] = av0.y;
        As[acq + 2][ar] = av0.z; As[acq + 3][ar] = av0.w;
        As[acq + 4][ar] = av1.x; As[acq + 5][ar] = av1.y;
        As[acq + 6][ar] = av1.z; As[acq + 7][ar] = av1.w;
        *(float4*)&Bs[bk][bn] = *(const float4*)&B[(k0 + bk) * ldb + col0 + bn];
        __syncthreads();
#pragma unroll
        for (int kk = 0; kk < 16; kk++) {
            ulonglong2 a01 = *(const ulonglong2*)&As[kk][ty << 3];
            ulonglong2 a23 = *(const ulonglong2*)&As[kk][(ty << 3) + 4];
            float4 b = *(const float4*)&Bs[kk][tx << 2];
            ull bb0 = pack2(b.x, b.x), bb1 = pack2(b.y, b.y);
            ull bb2 = pack2(b.z, b.z), bb3 = pack2(b.w, b.w);
            fma2(acc2[0][0], a01.x, bb0); fma2(acc2[0][1], a01.x, bb1);
            fma2(acc2[0][2], a01.x, bb2); fma2(acc2[0][3], a01.x, bb3);
            fma2(acc2[1][0], a01.y, bb0); fma2(acc2[1][1], a01.y, bb1);
            fma2(acc2[1][2], a01.y, bb2); fma2(acc2[1][3], a01.y, bb3);
            fma2(acc2[2][0], a23.x, bb0); fma2(acc2[2][1], a23.x, bb1);
            fma2(acc2[2][2], a23.x, bb2); fma2(acc2[2][3], a23.x, bb3);
            fma2(acc2[3][0], a23.y, bb0); fma2(acc2[3][1], a23.y, bb1);
            fma2(acc2[3][2], a23.y, bb2); fma2(acc2[3][3], a23.y, bb3);
        }
        __syncthreads();
    }
#pragma unroll
    for (int i2 = 0; i2 < 4; i2++) {
        int r = row0 + (ty << 3) + (i2 << 1);
#pragma unroll
        for (int j = 0; j < 4; j++) {
            int cc = col0 + (tx << 2) + j;
            float2 v = unpack2(acc2[i2][j]);
            float v0 = v.x + bias[cc];
            float v1 = v.y + bias[cc];
            if (act) {
                v0 = __fdividef(v0, 1.f + __expf(-v0));
                v1 = __fdividef(v1, 1.f + __expf(-v1));
            }
            C[r * ldc + cc] = v0;
            C[(r + 1) * ldc + cc] = v1;
        }
    }
}

__global__ __launch_bounds__(256) void sgemm128(
    const float* __restrict__ A0, const float* __restrict__ A1, int ksplit,
    int lda, const float* __restrict__ B, int ldb,
    const float* __restrict__ bias, float* __restrict__ C, int ldc, int K, int act)
{
    gemm_body(A0, A1, ksplit, lda, B, ldb, bias, C, ldc, K, act);
}

// q/k/v projections fused via blockIdx.z
__global__ __launch_bounds__(256) void qkv_kernel(
    const float* __restrict__ src, const float* __restrict__ tgt,
    const float* __restrict__ Wq, const float* __restrict__ bq,
    const float* __restrict__ Wk, const float* __restrict__ bk,
    const float* __restrict__ Wv, const float* __restrict__ bv)
{
    int z = blockIdx.z;
    const float* A = (z == 0) ? src : tgt;
    const float* W = (z == 0) ? Wq : ((z == 1) ? Wk : Wv);
    const float* b = (z == 0) ? bq : ((z == 1) ? bk : bv);
    float* C = (z == 0) ? g_q : ((z == 1) ? g_k : g_v);
    gemm_body(A, A, 256, 256, W, 256, b, C, 256, 256, 0);
}

// gate logits: 2 dots of length 1024 per node, then 2-way softmax
__global__ __launch_bounds__(256) void gate2_kernel(const float* __restrict__ w2,
                                                    const float* __restrict__ b2) {
    int n = blockIdx.x, tid = threadIdx.x;
    const float* hrow = g_gateh + n * 1024;
    float s0 = 0.f, s1 = 0.f;
#pragma unroll
    for (int t = 0; t < 4; t++) {
        int j = tid + 256 * t;
        float hv = hrow[j];
        s0 = fmaf(hv, w2[j * 2 + 0], s0);
        s1 = fmaf(hv, w2[j * 2 + 1], s1);
    }
    for (int o = 16; o; o >>= 1) {
        s0 += __shfl_xor_sync(~0u, s0, o);
        s1 += __shfl_xor_sync(~0u, s1, o);
    }
    __shared__ float r0[8], r1[8];
    if ((tid & 31) == 0) { r0[tid >> 5] = s0; r1[tid >> 5] = s1; }
    __syncthreads();
    if (tid == 0) {
        float l0 = b2[0], l1 = b2[1];
        for (int j = 0; j < 8; j++) { l0 += r0[j]; l1 += r1[j]; }
        float m = fmaxf(l0, l1);
        float e0 = __expf(l0 - m), e1 = __expf(l1 - m);
        float inv = __fdividef(1.f, e0 + e1);
        g_gate[n * 2 + 0] = e0 * inv;
        g_gate[n * 2 + 1] = e1 * inv;
    }
}

// ---------------- fused logits: QK/sqrt(D) + gate0*geoTbl(dist) + gate1*topo -
#define QPAD 260
#define LOGITS_SMEM ((64 * QPAD + 320) * 4)

__global__ __launch_bounds__(256) void logits_kernel(const float* __restrict__ pos)
{
    extern __shared__ float sh[];
    float* qs  = sh;                       // 32 x 260
    float* ks  = sh + 32 * QPAD;           // 32 x 260
    float* ext = sh + 64 * QPAD;
    float* sg0 = ext;                      // 32
    float* sg1 = sg0 + 32;                 // 32
    float* spn = sg1 + 32;                 // 32*3
    float* spm = spn + 96;                 // 32*3
    float* stt = spm + 96;                 // 16
    unsigned* spw = (unsigned*)(stt + 16); // 32

    int tid = threadIdx.x;
    int m0 = blockIdx.x * 32, n0 = blockIdx.y * 32;

#pragma unroll
    for (int t = 0; t < 8; t++) {
        int lin = tid + 256 * t;
        int r = lin >> 6, c4 = (lin & 63) << 2;
        *(float4*)&qs[r * QPAD + c4] = *(const float4*)&g_q[(n0 + r) * 256 + c4];
        *(float4*)&ks[r * QPAD + c4] = *(const float4*)&g_k[(m0 + r) * 256 + c4];
    }
    if (tid < 32) {
        sg0[tid] = g_gate[(n0 + tid) * 2 + 0];
        sg1[tid] = g_gate[(n0 + tid) * 2 + 1];
        spw[tid] = g_pa[(n0 + tid) * 32 + blockIdx.x];
        spn[tid * 3 + 0] = pos[(n0 + tid) * 3 + 0];
        spn[tid * 3 + 1] = pos[(n0 + tid) * 3 + 1];
        spn[tid * 3 + 2] = pos[(n0 + tid) * 3 + 2];
        spm[tid * 3 + 0] = pos[(m0 + tid) * 3 + 0];
        spm[tid * 3 + 1] = pos[(m0 + tid) * 3 + 1];
        spm[tid * 3 + 2] = pos[(m0 + tid) * 3 + 2];
    }
    if (tid < 16) stt[tid] = g_ttab[tid];
    __syncthreads();

    int mi = tid & 31, nbase = tid >> 5;
    float res[4][8];
    float px = spm[mi * 3 + 0], py = spm[mi * 3 + 1], pz = spm[mi * 3 + 2];

#pragma unroll
    for (int i = 0; i < 4; i++) {
        int ni = nbase + 8 * i;
        float dx = spn[ni * 3 + 0] - px;
        float dy = spn[ni * 3 + 1] - py;
        float dz = spn[ni * 3 + 2] - pz;
        float dist = sqrtf(fmaxf(dx * dx + dy * dy + dz * dz, 1e-12f));
        float gv0 = sg0[ni], gv1 = sg1[ni];
        int bit = (spw[ni] >> mi) & 1;

        float t = fminf(dist, TBL_MAX) * TBL_SCALE;
        int i0 = (int)t;
        if (i0 > TBL_N - 2) i0 = TBL_N - 2;
        float fr = t - (float)i0;
        const float4* tb = (const float4*)&g_tbl[i0 * 8];
        float4 r0 = __ldg(tb + 0), r1 = __ldg(tb + 1);
        float4 r2 = __ldg(tb + 2), r3 = __ldg(tb + 3);
        float a[8];
        a[0] = r0.x + fr * (r2.x - r0.x); a[1] = r0.y + fr * (r2.y - r0.y);
        a[2] = r0.z + fr * (r2.z - r0.z); a[3] = r0.w + fr * (r2.w - r0.w);
        a[4] = r1.x + fr * (r3.x - r1.x); a[5] = r1.y + fr * (r3.y - r1.y);
        a[6] = r1.z + fr * (r3.z - r1.z); a[7] = r1.w + fr * (r3.w - r1.w);
#pragma unroll
        for (int h = 0; h < 8; h++)
            res[i][h] = gv0 * a[h] + gv1 * stt[bit * 8 + h];
    }

    const float scale = 0.17677669529663687f;   // 1/sqrt(32)
#pragma unroll
    for (int h = 0; h < 8; h++) {
        float4 kr[8];
#pragma unroll
        for (int j = 0; j < 8; j++)
            kr[j] = *(const float4*)&ks[mi * QPAD + h * 32 + j * 4];
#pragma unroll
        for (int i = 0; i < 4; i++) {
            int ni = nbase + 8 * i;
            float s = 0.f;
#pragma unroll
            for (int j = 0; j < 8; j++) {
                float4 qv = *(const float4*)&qs[ni * QPAD + h * 32 + j * 4];
                s += qv.x * kr[j].x + qv.y * kr[j].y + qv.z * kr[j].z + qv.w * kr[j].w;
            }
            res[i][h] = fmaf(s, scale, res[i][h]);
        }
    }

#pragma unroll
    for (int i = 0; i < 4; i++) {
        int ng = n0 + nbase + 8 * i;
#pragma unroll
        for (int h = 0; h < 8; h++)
            g_logits[(ng * 8 + h) * 1024 + m0 + mi] = res[i][h];
    }
}

// ---------------- row stats (max, 1/sum of exp) -------------------------------
__global__ __launch_bounds__(256) void stats_kernel() {
    int row = blockIdx.x;
    const float* p = g_logits + (long)row * 1024;
    int tid = threadIdx.x;
    float4 v = *(const float4*)&p[tid * 4];
    float mx = fmaxf(fmaxf(v.x, v.y), fmaxf(v.z, v.w));
    for (int o = 16; o; o >>= 1) mx = fmaxf(mx, __shfl_xor_sync(~0u, mx, o));
    __shared__ float rm[8], rs[8];
    if ((tid & 31) == 0) rm[tid >> 5] = mx;
    __syncthreads();
    mx = rm[0];
#pragma unroll
    for (int j = 1; j < 8; j++) mx = fmaxf(mx, rm[j]);
    float s = __expf(v.x - mx) + __expf(v.y - mx) + __expf(v.z - mx) + __expf(v.w - mx);
    for (int o = 16; o; o >>= 1) s += __shfl_xor_sync(~0u, s, o);
    if ((tid & 31) == 0) rs[tid >> 5] = s;
    __syncthreads();
    if (tid == 0) {
        float tot = 0.f;
#pragma unroll
        for (int j = 0; j < 8; j++) tot += rs[j];
        g_stats[row] = make_float2(mx, __fdividef(1.f, tot));
    }
}

// -------- PV with inline softmax: out[n,h*32+d] = sum_m p[n,h,m] v[m,h*32+d] -
__global__ __launch_bounds__(256) void pv_kernel() {
    int h = blockIdx.x, n0 = blockIdx.y * 64;
    __shared__ float As[64][36];   // n x m (softmaxed probs)
    __shared__ float Bs[32][32];   // m x d
    __shared__ float2 sstat[64];
    int tid = threadIdx.x;
    int dxi = tid & 31;
    int ty = tid >> 5;
    if (tid < 64) sstat[tid] = g_stats[(n0 + tid) * 8 + h];
    __syncthreads();
    float acc[8];
#pragma unroll
    for (int i = 0; i < 8; i++) acc[i] = 0.f;

    for (int m0 = 0; m0 < 1024; m0 += 32) {
#pragma unroll
        for (int t = 0; t < 2; t++) {
            int lin = tid + 256 * t;
            int r = lin >> 3, c4 = (lin & 7) << 2;
            float4 v = *(const float4*)&g_logits[((long)(n0 + r) * 8 + h) * 1024 + m0 + c4];
            float2 st = sstat[r];
            v.x = __expf(v.x - st.x) * st.y;
            v.y = __expf(v.y - st.x) * st.y;
            v.z = __expf(v.z - st.x) * st.y;
            v.w = __expf(v.w - st.x) * st.y;
            *(float4*)&As[r][c4] = v;
        }
        {
            int r = tid >> 3, c4 = (tid & 7) << 2;
            *(float4*)&Bs[r][c4] = *(const float4*)&g_v[(m0 + r) * 256 + h * 32 + c4];
        }
        __syncthreads();
#pragma unroll
        for (int mm = 0; mm < 32; mm += 4) {
            float b0 = Bs[mm + 0][dxi], b1 = Bs[mm + 1][dxi];
            float b2 = Bs[mm + 2][dxi], b3 = Bs[mm + 3][dxi];
#pragma unroll
            for (int i = 0; i < 8; i++) {
                float4 a = *(const float4*)&As[ty + 8 * i][mm];
                acc[i] = fmaf(a.x, b0, fmaf(a.y, b1, fmaf(a.z, b2, fmaf(a.w, b3, acc[i]))));
            }
        }
        __syncthreads();
    }
#pragma unroll
    for (int i = 0; i < 8; i++)
        g_attnout[(n0 + ty + 8 * i) * 256 + h * 32 + dxi] = acc[i];
}

// ---------------- residual + layernorm ----------------------------------------
__global__ __launch_bounds__(256) void ln_kernel(const float* __restrict__ src,
                                                 const float* __restrict__ g,
                                                 const float* __restrict__ b,
                                                 float* __restrict__ out) {
    int n = blockIdx.x, tid = threadIdx.x;
    float x = src[n * 256 + tid] + g_proj[n * 256 + tid];
    float s = x;
    for (int o = 16; o; o >>= 1) s += __shfl_xor_sync(~0u, s, o);
    __shared__ float r1[8], r2[8];
    if ((tid & 31) == 0) r1[tid >> 5] = s;
    __syncthreads();
    float tot = 0.f;
#pragma unroll
    for (int j = 0; j < 8; j++) tot += r1[j];
    float mu = tot * (1.f / 256.f);
    float d = x - mu;
    float s2 = d * d;
    for (int o = 16; o; o >>= 1) s2 += __shfl_xor_sync(~0u, s2, o);
    if ((tid & 31) == 0) r2[tid >> 5] = s2;
    __syncthreads();
    float var = 0.f;
#pragma unroll
    for (int j = 0; j < 8; j++) var += r2[j];
    var *= (1.f / 256.f);
    out[n * 256 + tid] = d * rsqrtf(var + 1e-5f) * g[tid] + b[tid];
}

// ---------------- launch ------------------------------------------------------
extern "C" void kernel_launch(void* const* d_in, const int* in_sizes, int n_in,
                              void* d_out, int out_size) {
    const float* src_feat = (const float*)d_in[0];
    const float* tgt_feat = (const float*)d_in[1];
    const float* src_pos  = (const float*)d_in[2];
    const void*  edges    = d_in[3];
    const float* Wq = (const float*)d_in[4],  *bq = (const float*)d_in[5];
    const float* Wk = (const float*)d_in[6],  *bk = (const float*)d_in[7];
    const float* Wv = (const float*)d_in[8],  *bv = (const float*)d_in[9];
    const float* geo_w1 = (const float*)d_in[10], *geo_b1 = (const float*)d_in[11];
    const float* geo_w2 = (const float*)d_in[12], *geo_b2 = (const float*)d_in[13];
    const float* top_w1 = (const float*)d_in[14], *top_b1 = (const float*)d_in[15];
    const float* top_w2 = (const float*)d_in[16], *top_b2 = (const float*)d_in[17];
    const float* gate_w1 = (const float*)d_in[18], *gate_b1 = (const float*)d_in[19];
    const float* gate_w2 = (const float*)d_in[20], *gate_b2 = (const float*)d_in[21];
    const float* Wo = (const float*)d_in[22], *bo = (const float*)d_in[23];
    const float* ln_g = (const float*)d_in[24], *ln_b = (const float*)d_in[25];
    float* out = (float*)d_out;

    void *pgateh, *pattn, *pproj;
    cudaGetSymbolAddress(&pgateh, g_gateh);
    cudaGetSymbolAddress(&pattn, g_attnout);
    cudaGetSymbolAddress(&pproj, g_proj);

    cudaFuncSetAttribute(logits_kernel,
                         cudaFuncAttributeMaxDynamicSharedMemorySize, LOGITS_SMEM);

    // 1: geo table + zero adj + ttab (fused setup)
    setup_kernel<<<33, 256>>>(geo_w1, geo_b1, geo_w2, geo_b2,
                              top_w1, top_b1, top_w2, top_b2);
    // 2: scatter edges (inline dtype detect)
    scatter_edges_kernel<<<64, 256>>>((const unsigned*)edges);
    // 3: path round 1
    path_round_kernel<<<128, 256>>>(0);
    // 4: gate MLP GEMM (positioned for ncu capture): 1024x1024, K=512, 128 blocks
    sgemm128<<<dim3(16, 8), 256>>>(src_feat, tgt_feat, 256, 256, gate_w1, 1024,
                                   gate_b1, (float*)pgateh, 1024, 512, 1);
    // 5-6: path rounds 2,3 (final path in g_pa)
    path_round_kernel<<<128, 256>>>(1);
    path_round_kernel<<<128, 256>>>(2);
    // 7: q/k/v projections: 96 blocks
    qkv_kernel<<<dim3(4, 8, 3), 256>>>(src_feat, tgt_feat, Wq, bq, Wk, bk, Wv, bv);
    // 8: gate head + 2-way softmax
    gate2_kernel<<<1024, 256>>>(gate_w2, gate_b2);
    // 9-11: fused logits, row stats, PV
    logits_kernel<<<dim3(32, 32), 256, LOGITS_SMEM>>>(src_pos);
    stats_kernel<<<8192, 256>>>();
    pv_kernel<<<dim3(8, 16), 256>>>();
    // 12: output projection
    sgemm128<<<dim3(4, 8), 256>>>((const float*)pattn, (const float*)pattn, 256, 256,
                                  Wo, 256, bo, (float*)pproj, 256, 256, 0);
    // 13: residual + layernorm
    ln_kernel<<<1024, 256>>>(src_feat, ln_g, ln_b, out);
}

// round 13
// speedup vs baseline: 1.1275x; 1.0579x over previous
#include <cuda_runtime.h>
#include <cuda_bf16.h>

#define NN 1024
#define HID 256
#define NH 8
#define HD 32
#define NE 16384

#define TBL_N 8192
#define TBL_MAX 24.0f
#define TBL_SCALE ((float)(TBL_N - 1) / TBL_MAX)

// ---------------- scratch (static device memory; no allocations) -------------
__device__ float    g_q[NN * HID];
__device__ float    g_k[NN * HID];
__device__ float    g_v[NN * HID];
__device__ float    g_gateh[NN * 4 * HID];
__device__ float    g_gate[NN * 2];
__device__ unsigned g_adj[NN * 32];
__device__ unsigned g_pa[NN * 32];
__device__ unsigned g_pb[NN * 32];
__device__ float    g_ttab[16];                  // [path_val(0/1)][head]
__device__ float    g_tbl[TBL_N * 8];            // geo MLP lookup table [i][h]
__device__ float    g_logits[NN * NH * NN];      // 32 MB, [n][h][m], raw logits
__device__ float2   g_stats[NN * NH];            // per-row (max, 1/sum)
__device__ float    g_attnout[NN * HID];
__device__ float    g_proj[NN * HID];

// ------- setup: geo table (blocks 0-31) + zero adj slices + ttab (block 32) --
__global__ void setup_kernel(const float* __restrict__ gw1, const float* __restrict__ gb1,
                             const float* __restrict__ gw2, const float* __restrict__ gb2,
                             const float* __restrict__ tw1, const float* __restrict__ tb1,
                             const float* __restrict__ tw2, const float* __restrict__ tb2) {
    int b = blockIdx.x, tid = threadIdx.x;
    if (b < 32) {
#pragma unroll
        for (int t = 0; t < 4; t++) g_adj[b * 1024 + tid + 256 * t] = 0u;
        int i = b * 256 + tid;
        float dist = (float)i * (TBL_MAX / (float)(TBL_N - 1));
        float a[8];
#pragma unroll
        for (int h = 0; h < 8; h++) a[h] = gb2[h];
        for (int c = 0; c < 32; c++) {
            float hv = fmaf(dist, gw1[c], gb1[c]);
            float s = __fdividef(hv, 1.f + __expf(-hv));
#pragma unroll
            for (int h = 0; h < 8; h++) a[h] = fmaf(s, gw2[c * 8 + h], a[h]);
        }
#pragma unroll
        for (int h = 0; h < 8; h++) g_tbl[i * 8 + h] = a[h];
    } else {
        if (tid < 16) {
            float pv = (float)(tid >> 3);
            int h = tid & 7;
            float acc = tb2[h];
            for (int c = 0; c < 32; c++) {
                float hv = fmaf(pv, tw1[c], tb1[c]);
                float s = __fdividef(hv, 1.f + __expf(-hv));
                acc = fmaf(s, tw2[c * 8 + h], acc);
            }
            g_ttab[tid] = acc;
        }
    }
}

// ---------------- scatter edges with inline dtype detect ----------------------
__global__ void scatter_edges_kernel(const unsigned* __restrict__ w) {
    bool is64 = true;
#pragma unroll
    for (int i = 1; i < 16; i += 2) is64 &= (w[i] == 0u);
    int e = blockIdx.x * blockDim.x + threadIdx.x;
    if (e >= NE) return;
    int s, d;
    if (is64) {
        const long long* p = (const long long*)w;
        s = (int)p[e];
        d = (int)p[NE + e];
    } else {
        const int* p = (const int*)w;
        s = p[e];
        d = p[NE + e];
    }
    atomicOr(&g_adj[s * 32 + (d >> 5)], 1u << (d & 31));
}

// path = min(path, path @ adj): binary reachability step on bitsets.
#define LIST_CAP 512
__global__ __launch_bounds__(256) void path_round_kernel(int r) {
    const unsigned* in = (r == 0) ? g_adj : ((r == 1) ? g_pa : g_pb);
    unsigned* out = (r == 1) ? g_pb : g_pa;
    __shared__ unsigned short lists[8][LIST_CAP];
    int warp = threadIdx.x >> 5, lane = threadIdx.x & 31;
    int row = blockIdx.x * 8 + warp;
    unsigned w = in[row * 32 + lane];
    int c = __popc(w);
    int pre = c;
#pragma unroll
    for (int o = 1; o < 32; o <<= 1) {
        int x = __shfl_up_sync(~0u, pre, o);
        if (lane >= o) pre += x;
    }
    int total = __shfl_sync(~0u, pre, 31);
    unsigned acc = 0u;
    if (total <= LIST_CAP) {
        int k = pre - c;
        unsigned tmp = w;
        while (tmp) {
            int b = __ffs(tmp) - 1; tmp &= tmp - 1;
            lists[warp][k++] = (unsigned short)(lane * 32 + b);
        }
        __syncwarp();
        int j = 0;
        for (; j + 8 <= total; j += 8) {
            unsigned a0 = g_adj[lists[warp][j + 0] * 32 + lane];
            unsigned a1 = g_adj[lists[warp][j + 1] * 32 + lane];
            unsigned a2 = g_adj[lists[warp][j + 2] * 32 + lane];
            unsigned a3 = g_adj[lists[warp][j + 3] * 32 + lane];
            unsigned a4 = g_adj[lists[warp][j + 4] * 32 + lane];
            unsigned a5 = g_adj[lists[warp][j + 5] * 32 + lane];
            unsigned a6 = g_adj[lists[warp][j + 6] * 32 + lane];
            unsigned a7 = g_adj[lists[warp][j + 7] * 32 + lane];
            acc |= (a0 | a1) | (a2 | a3) | (a4 | a5) | (a6 | a7);
        }
        for (; j < total; j++) acc |= g_adj[lists[warp][j] * 32 + lane];
    } else {
        for (int ww = 0; ww < 32; ww++) {
            unsigned word = __shfl_sync(~0u, w, ww);
            while (word) {
                int b = __ffs(word) - 1; word &= word - 1;
                acc |= g_adj[(ww * 32 + b) * 32 + lane];
            }
        }
    }
    out[row * 32 + lane] = w & acc;
}

// ---------------- 64x64 tiled SGEMM body, C = [A0|A1]@B + bias [, silu] ------
// (R9-verified body: 256 thr, 4x4 microtile)
__device__ __forceinline__ void gemm_body(
    const float* __restrict__ A0, const float* __restrict__ A1, int ksplit,
    int lda, const float* __restrict__ B, int ldb,
    const float* __restrict__ bias, float* __restrict__ C, int ldc, int K, int act)
{
    __shared__ float As[16][68];
    __shared__ float Bs[16][64];
    int tid = threadIdx.x;
    int tx = tid & 15, ty = tid >> 4;
    int row0 = blockIdx.y * 64, col0 = blockIdx.x * 64;
    float acc[4][4];
#pragma unroll
    for (int i = 0; i < 4; i++)
#pragma unroll
        for (int j = 0; j < 4; j++) acc[i][j] = 0.f;
    int ar = tid >> 2, ac = (tid & 3) << 2;
    int bk = tid >> 4, bn = (tid & 15) << 2;
    for (int k0 = 0; k0 < K; k0 += 16) {
        const float* Ap = (k0 < ksplit)
            ? &A0[(row0 + ar) * lda + k0 + ac]
            : &A1[(row0 + ar) * lda + (k0 - ksplit) + ac];
        float4 av = *(const float4*)Ap;
        As[ac + 0][ar] = av.x; As[ac + 1][ar] = av.y;
        As[ac + 2][ar] = av.z; As[ac + 3][ar] = av.w;
        *(float4*)&Bs[bk][bn] = *(const float4*)&B[(k0 + bk) * ldb + col0 + bn];
        __syncthreads();
#pragma unroll
        for (int kk = 0; kk < 16; kk++) {
            float4 a = *(const float4*)&As[kk][ty << 2];
            float4 b = *(const float4*)&Bs[kk][tx << 2];
            acc[0][0] = fmaf(a.x, b.x, acc[0][0]); acc[0][1] = fmaf(a.x, b.y, acc[0][1]);
            acc[0][2] = fmaf(a.x, b.z, acc[0][2]); acc[0][3] = fmaf(a.x, b.w, acc[0][3]);
            acc[1][0] = fmaf(a.y, b.x, acc[1][0]); acc[1][1] = fmaf(a.y, b.y, acc[1][1]);
            acc[1][2] = fmaf(a.y, b.z, acc[1][2]); acc[1][3] = fmaf(a.y, b.w, acc[1][3]);
            acc[2][0] = fmaf(a.z, b.x, acc[2][0]); acc[2][1] = fmaf(a.z, b.y, acc[2][1]);
            acc[2][2] = fmaf(a.z, b.z, acc[2][2]); acc[2][3] = fmaf(a.z, b.w, acc[2][3]);
            acc[3][0] = fmaf(a.w, b.x, acc[3][0]); acc[3][1] = fmaf(a.w, b.y, acc[3][1]);
            acc[3][2] = fmaf(a.w, b.z, acc[3][2]); acc[3][3] = fmaf(a.w, b.w, acc[3][3]);
        }
        __syncthreads();
    }
#pragma unroll
    for (int i = 0; i < 4; i++) {
        int r = row0 + (ty << 2) + i;
#pragma unroll
        for (int j = 0; j < 4; j++) {
            int cc = col0 + (tx << 2) + j;
            float v = acc[i][j] + bias[cc];
            if (act) v = __fdividef(v, 1.f + __expf(-v));
            C[r * ldc + cc] = v;
        }
    }
}

__global__ __launch_bounds__(256) void sgemm64(
    const float* __restrict__ A0, const float* __restrict__ A1, int ksplit,
    int lda, const float* __restrict__ B, int ldb,
    const float* __restrict__ bias, float* __restrict__ C, int ldc, int K, int act)
{
    gemm_body(A0, A1, ksplit, lda, B, ldb, bias, C, ldc, K, act);
}

// q/k/v projections fused via blockIdx.z
__global__ __launch_bounds__(256) void qkv_kernel(
    const float* __restrict__ src, const float* __restrict__ tgt,
    const float* __restrict__ Wq, const float* __restrict__ bq,
    const float* __restrict__ Wk, const float* __restrict__ bk,
    const float* __restrict__ Wv, const float* __restrict__ bv)
{
    int z = blockIdx.z;
    const float* A = (z == 0) ? src : tgt;
    const float* W = (z == 0) ? Wq : ((z == 1) ? Wk : Wv);
    const float* b = (z == 0) ? bq : ((z == 1) ? bk : bv);
    float* C = (z == 0) ? g_q : ((z == 1) ? g_k : g_v);
    gemm_body(A, A, 256, 256, W, 256, b, C, 256, 256, 0);
}

// gate logits: 2 dots of length 1024 per node, then 2-way softmax
__global__ __launch_bounds__(256) void gate2_kernel(const float* __restrict__ w2,
                                                    const float* __restrict__ b2) {
    int n = blockIdx.x, tid = threadIdx.x;
    const float* hrow = g_gateh + n * 1024;
    float s0 = 0.f, s1 = 0.f;
#pragma unroll
    for (int t = 0; t < 4; t++) {
        int j = tid + 256 * t;
        float hv = hrow[j];
        s0 = fmaf(hv, w2[j * 2 + 0], s0);
        s1 = fmaf(hv, w2[j * 2 + 1], s1);
    }
    for (int o = 16; o; o >>= 1) {
        s0 += __shfl_xor_sync(~0u, s0, o);
        s1 += __shfl_xor_sync(~0u, s1, o);
    }
    __shared__ float r0[8], r1[8];
    if ((tid & 31) == 0) { r0[tid >> 5] = s0; r1[tid >> 5] = s1; }
    __syncthreads();
    if (tid == 0) {
        float l0 = b2[0], l1 = b2[1];
        for (int j = 0; j < 8; j++) { l0 += r0[j]; l1 += r1[j]; }
        float m = fmaxf(l0, l1);
        float e0 = __expf(l0 - m), e1 = __expf(l1 - m);
        float inv = __fdividef(1.f, e0 + e1);
        g_gate[n * 2 + 0] = e0 * inv;
        g_gate[n * 2 + 1] = e1 * inv;
    }
}

// ======== logits: 64n x 32m tile, thread = 4n x 2m x 4h, 2 head-groups =======
// smem float offsets
#define LQ_QS   0                       // [64][132]
#define LQ_KS   8448                    // [32][132]
#define LQ_SPN  12672                   // 192
#define LQ_SPM  12864                   // 96
#define LQ_SG0  12960                   // 64
#define LQ_SG1  13024                   // 64
#define LQ_STT  13088                   // 16
#define LQ_SPW  13104                   // 64 (unsigned)
#define LOGITS_SMEM ((13104 + 64) * 4)

__global__ __launch_bounds__(256) void logits_kernel(const float* __restrict__ pos)
{
    extern __shared__ float sh[];
    float* qs = sh + LQ_QS;
    float* ks = sh + LQ_KS;
    float* spn = sh + LQ_SPN;
    float* spm = sh + LQ_SPM;
    float* sg0 = sh + LQ_SG0;
    float* sg1 = sh + LQ_SG1;
    float* stt = sh + LQ_STT;
    unsigned* spw = (unsigned*)(sh + LQ_SPW);

    int tid = threadIdx.x;
    int tx = tid & 15, ty = tid >> 4;       // tx: m-group, ty: n-group
    int m0 = blockIdx.x * 32, n0 = blockIdx.y * 64;
    const float scale = 0.17677669529663687f;   // 1/sqrt(32)

    if (tid < 192) spn[tid] = pos[n0 * 3 + tid];
    if (tid < 96)  spm[tid] = pos[m0 * 3 + tid];
    if (tid < 64) {
        sg0[tid] = g_gate[(n0 + tid) * 2 + 0];
        sg1[tid] = g_gate[(n0 + tid) * 2 + 1];
        spw[tid] = g_pa[(n0 + tid) * 32 + (m0 >> 5)];
    }
    if (tid < 16) stt[tid] = g_ttab[tid];
    __syncthreads();

    // per-pair precompute: 4n x 2m = 8 pairs, all in registers
    int i0r[8]; float frr[8]; unsigned bitm = 0;
#pragma unroll
    for (int i = 0; i < 4; i++) {
        int n = ty * 4 + i;
        float pnx = spn[n * 3 + 0], pny = spn[n * 3 + 1], pnz = spn[n * 3 + 2];
#pragma unroll
        for (int j = 0; j < 2; j++) {
            int m = tx + 16 * j;
            float dx = pnx - spm[m * 3 + 0];
            float dy = pny - spm[m * 3 + 1];
            float dz = pnz - spm[m * 3 + 2];
            float dist = sqrtf(fmaxf(dx * dx + dy * dy + dz * dz, 1e-12f));
            float t = fminf(dist, TBL_MAX) * TBL_SCALE;
            int i0 = (int)t;
            if (i0 > TBL_N - 2) i0 = TBL_N - 2;
            int p = i * 2 + j;
            i0r[p] = i0;
            frr[p] = t - (float)i0;
            bitm |= ((spw[n] >> m) & 1u) << p;
        }
    }

    for (int g = 0; g < 2; g++) {
        __syncthreads();   // protect qs/ks before overwrite
        // load tiles: dims g*128 .. g*128+127 (heads 4g..4g+3)
        for (int l = tid; l < 2048; l += 256) {
            int r = l >> 5, c4 = (l & 31) << 2;
            *(float4*)&qs[r * 132 + c4] =
                *(const float4*)&g_q[(n0 + r) * 256 + g * 128 + c4];
        }
        for (int l = tid; l < 1024; l += 256) {
            int r = l >> 5, c4 = (l & 31) << 2;
            *(float4*)&ks[r * 132 + c4] =
                *(const float4*)&g_k[(m0 + r) * 256 + g * 128 + c4];
        }
        __syncthreads();

        float res[4][4][2];   // [hh][i][j]
#pragma unroll
        for (int hh = 0; hh < 4; hh++)
#pragma unroll
            for (int i = 0; i < 4; i++) { res[hh][i][0] = 0.f; res[hh][i][1] = 0.f; }

#pragma unroll
        for (int dd = 0; dd < 128; dd += 4) {
            const int hh = dd >> 5;
            float4 qv[4], kv[2];
#pragma unroll
            for (int i = 0; i < 4; i++)
                qv[i] = *(const float4*)&qs[(ty * 4 + i) * 132 + dd];
            kv[0] = *(const float4*)&ks[tx * 132 + dd];
            kv[1] = *(const float4*)&ks[(tx + 16) * 132 + dd];
#pragma unroll
            for (int i = 0; i < 4; i++) {
#pragma unroll
                for (int j = 0; j < 2; j++) {
                    res[hh][i][j] = fmaf(qv[i].x, kv[j].x,
                                    fmaf(qv[i].y, kv[j].y,
                                    fmaf(qv[i].z, kv[j].z,
                                    fmaf(qv[i].w, kv[j].w, res[hh][i][j]))));
                }
            }
        }

        // epilogue: bias + store
        float tt0[4], tt1[4];
#pragma unroll
        for (int hh = 0; hh < 4; hh++) {
            tt0[hh] = stt[4 * g + hh];
            tt1[hh] = stt[8 + 4 * g + hh];
        }
#pragma unroll
        for (int i = 0; i < 4; i++) {
            int n = ty * 4 + i;
            float g0v = sg0[n], g1v = sg1[n];
#pragma unroll
            for (int j = 0; j < 2; j++) {
                int p = i * 2 + j, m = tx + 16 * j;
                int i0 = i0r[p]; float fr = frr[p];
                float4 ta = __ldg((const float4*)&g_tbl[i0 * 8 + 4 * g]);
                float4 tb = __ldg((const float4*)&g_tbl[(i0 + 1) * 8 + 4 * g]);
                float geo[4];
                geo[0] = ta.x + fr * (tb.x - ta.x);
                geo[1] = ta.y + fr * (tb.y - ta.y);
                geo[2] = ta.z + fr * (tb.z - ta.z);
                geo[3] = ta.w + fr * (tb.w - ta.w);
                int bit = (bitm >> p) & 1;
                int base = ((n0 + n) * 8 + 4 * g) * 1024 + m0 + m;
#pragma unroll
                for (int hh = 0; hh < 4; hh++) {
                    float bias = g0v * geo[hh] + g1v * (bit ? tt1[hh] : tt0[hh]);
                    g_logits[base + hh * 1024] = fmaf(res[hh][i][j], scale, bias);
                }
            }
        }
    }
}

// ---------------- row stats (max, 1/sum of exp) -------------------------------
__global__ __launch_bounds__(256) void stats_kernel() {
    int row = blockIdx.x;
    const float* p = g_logits + (long)row * 1024;
    int tid = threadIdx.x;
    float4 v = *(const float4*)&p[tid * 4];
    float mx = fmaxf(fmaxf(v.x, v.y), fmaxf(v.z, v.w));
    for (int o = 16; o; o >>= 1) mx = fmaxf(mx, __shfl_xor_sync(~0u, mx, o));
    __shared__ float rm[8], rs[8];
    if ((tid & 31) == 0) rm[tid >> 5] = mx;
    __syncthreads();
    mx = rm[0];
#pragma unroll
    for (int j = 1; j < 8; j++) mx = fmaxf(mx, rm[j]);
    float s = __expf(v.x - mx) + __expf(v.y - mx) + __expf(v.z - mx) + __expf(v.w - mx);
    for (int o = 16; o; o >>= 1) s += __shfl_xor_sync(~0u, s, o);
    if ((tid & 31) == 0) rs[tid >> 5] = s;
    __syncthreads();
    if (tid == 0) {
        float tot = 0.f;
#pragma unroll
        for (int j = 0; j < 8; j++) tot += rs[j];
        g_stats[row] = make_float2(mx, __fdividef(1.f, tot));
    }
}

// -------- PV with inline softmax: out[n,h*32+d] = sum_m p[n,h,m] v[m,h*32+d] -
__global__ __launch_bounds__(256) void pv_kernel() {
    int h = blockIdx.x, n0 = blockIdx.y * 64;
    __shared__ float As[64][36];   // n x m (softmaxed probs)
    __shared__ float Bs[32][32];   // m x d
    __shared__ float2 sstat[64];
    int tid = threadIdx.x;
    int dxi = tid & 31;
    int ty = tid >> 5;
    if (tid < 64) sstat[tid] = g_stats[(n0 + tid) * 8 + h];
    __syncthreads();
    float acc[8];
#pragma unroll
    for (int i = 0; i < 8; i++) acc[i] = 0.f;

    for (int m0 = 0; m0 < 1024; m0 += 32) {
#pragma unroll
        for (int t = 0; t < 2; t++) {
            int lin = tid + 256 * t;
            int r = lin >> 3, c4 = (lin & 7) << 2;
            float4 v = *(const float4*)&g_logits[((long)(n0 + r) * 8 + h) * 1024 + m0 + c4];
            float2 st = sstat[r];
            v.x = __expf(v.x - st.x) * st.y;
            v.y = __expf(v.y - st.x) * st.y;
            v.z = __expf(v.z - st.x) * st.y;
            v.w = __expf(v.w - st.x) * st.y;
            *(float4*)&As[r][c4] = v;
        }
        {
            int r = tid >> 3, c4 = (tid & 7) << 2;
            *(float4*)&Bs[r][c4] = *(const float4*)&g_v[(m0 + r) * 256 + h * 32 + c4];
        }
        __syncthreads();
#pragma unroll
        for (int mm = 0; mm < 32; mm += 4) {
            float b0 = Bs[mm + 0][dxi], b1 = Bs[mm + 1][dxi];
            float b2 = Bs[mm + 2][dxi], b3 = Bs[mm + 3][dxi];
#pragma unroll
            for (int i = 0; i < 8; i++) {
                float4 a = *(const float4*)&As[ty + 8 * i][mm];
                acc[i] = fmaf(a.x, b0, fmaf(a.y, b1, fmaf(a.z, b2, fmaf(a.w, b3, acc[i]))));
            }
        }
        __syncthreads();
    }
#pragma unroll
    for (int i = 0; i < 8; i++)
        g_attnout[(n0 + ty + 8 * i) * 256 + h * 32 + dxi] = acc[i];
}

// ---------------- residual + layernorm ----------------------------------------
__global__ __launch_bounds__(256) void ln_kernel(const float* __restrict__ src,
                                                 const float* __restrict__ g,
                                                 const float* __restrict__ b,
                                                 float* __restrict__ out) {
    int n = blockIdx.x, tid = threadIdx.x;
    float x = src[n * 256 + tid] + g_proj[n * 256 + tid];
    float s = x;
    for (int o = 16; o; o >>= 1) s += __shfl_xor_sync(~0u, s, o);
    __shared__ float r1[8], r2[8];
    if ((tid & 31) == 0) r1[tid >> 5] = s;
    __syncthreads();
    float tot = 0.f;
#pragma unroll
    for (int j = 0; j < 8; j++) tot += r1[j];
    float mu = tot * (1.f / 256.f);
    float d = x - mu;
    float s2 = d * d;
    for (int o = 16; o; o >>= 1) s2 += __shfl_xor_sync(~0u, s2, o);
    if ((tid & 31) == 0) r2[tid >> 5] = s2;
    __syncthreads();
    float var = 0.f;
#pragma unroll
    for (int j = 0; j < 8; j++) var += r2[j];
    var *= (1.f / 256.f);
    out[n * 256 + tid] = d * rsqrtf(var + 1e-5f) * g[tid] + b[tid];
}

// ---------------- launch ------------------------------------------------------
extern "C" void kernel_launch(void* const* d_in, const int* in_sizes, int n_in,
                              void* d_out, int out_size) {
    const float* src_feat = (const float*)d_in[0];
    const float* tgt_feat = (const float*)d_in[1];
    const float* src_pos  = (const float*)d_in[2];
    const void*  edges    = d_in[3];
    const float* Wq = (const float*)d_in[4],  *bq = (const float*)d_in[5];
    const float* Wk = (const float*)d_in[6],  *bk = (const float*)d_in[7];
    const float* Wv = (const float*)d_in[8],  *bv = (const float*)d_in[9];
    const float* geo_w1 = (const float*)d_in[10], *geo_b1 = (const float*)d_in[11];
    const float* geo_w2 = (const float*)d_in[12], *geo_b2 = (const float*)d_in[13];
    const float* top_w1 = (const float*)d_in[14], *top_b1 = (const float*)d_in[15];
    const float* top_w2 = (const float*)d_in[16], *top_b2 = (const float*)d_in[17];
    const float* gate_w1 = (const float*)d_in[18], *gate_b1 = (const float*)d_in[19];
    const float* gate_w2 = (const float*)d_in[20], *gate_b2 = (const float*)d_in[21];
    const float* Wo = (const float*)d_in[22], *bo = (const float*)d_in[23];
    const float* ln_g = (const float*)d_in[24], *ln_b = (const float*)d_in[25];
    float* out = (float*)d_out;

    void *pgateh, *pattn, *pproj;
    cudaGetSymbolAddress(&pgateh, g_gateh);
    cudaGetSymbolAddress(&pattn, g_attnout);
    cudaGetSymbolAddress(&pproj, g_proj);

    cudaFuncSetAttribute(logits_kernel,
                         cudaFuncAttributeMaxDynamicSharedMemorySize, LOGITS_SMEM);

    // 1: geo table + zero adj + ttab (fused setup)
    setup_kernel<<<33, 256>>>(geo_w1, geo_b1, geo_w2, geo_b2,
                              top_w1, top_b1, top_w2, top_b2);
    // 2: scatter edges (inline dtype detect)
    scatter_edges_kernel<<<64, 256>>>((const unsigned*)edges);
    // 3: path round 1
    path_round_kernel<<<128, 256>>>(0);
    // 4: gate MLP GEMM (positioned for ncu capture): 1024x1024, K=512, 256 blocks
    sgemm64<<<dim3(16, 16), 256>>>(src_feat, tgt_feat, 256, 256, gate_w1, 1024,
                                   gate_b1, (float*)pgateh, 1024, 512, 1);
    // 5-6: path rounds 2,3 (final path in g_pa)
    path_round_kernel<<<128, 256>>>(1);
    path_round_kernel<<<128, 256>>>(2);
    // 7: q/k/v projections (192 blocks)
    qkv_kernel<<<dim3(4, 16, 3), 256>>>(src_feat, tgt_feat, Wq, bq, Wk, bk, Wv, bv);
    // 8: gate head + 2-way softmax
    gate2_kernel<<<1024, 256>>>(gate_w2, gate_b2);
    // 9-11: fused logits (512 blocks), row stats, PV
    logits_kernel<<<dim3(32, 16), 256, LOGITS_SMEM>>>(src_pos);
    stats_kernel<<<8192, 256>>>();
    pv_kernel<<<dim3(8, 16), 256>>>();
    // 12: output projection
    sgemm64<<<dim3(4, 16), 256>>>((const float*)pattn, (const float*)pattn, 256, 256,
                                  Wo, 256, bo, (float*)pproj, 256, 256, 0);
    // 13: residual + layernorm
    ln_kernel<<<1024, 256>>>(src_feat, ln_g, ln_b, out);
}

// round 15
// speedup vs baseline: 1.1642x; 1.0325x over previous
#include <cuda_runtime.h>
#include <cuda_bf16.h>

#define NN 1024
#define HID 256
#define NH 8
#define HD 32
#define NE 16384

#define TBL_N 8192
#define TBL_MAX 24.0f
#define TBL_SCALE ((float)(TBL_N - 1) / TBL_MAX)

// ---------------- scratch (static device memory; no allocations) -------------
__device__ float    g_q[NN * HID];
__device__ float    g_k[NN * HID];
__device__ float    g_v[NN * HID];
__device__ float    g_gateh[NN * 4 * HID];
__device__ float    g_gate[NN * 2];
__device__ unsigned g_adj[NN * 32];
__device__ unsigned g_pa[NN * 32];
__device__ unsigned g_pb[NN * 32];
__device__ float    g_ttab[16];                  // [path_val(0/1)][head]
__device__ float    g_tbl[TBL_N * 8];            // geo MLP lookup table [i][h]
__device__ float    g_logits[NN * NH * NN];      // 32 MB, [n][h][m], raw logits
__device__ float2   g_stats[NN * NH];            // per-row (max, 1/sum)
__device__ float    g_attnout[NN * HID];
__device__ float    g_proj[NN * HID];

// ------- setup: geo table (blocks 0-31) + zero adj slices + ttab (block 32) --
__global__ void setup_kernel(const float* __restrict__ gw1, const float* __restrict__ gb1,
                             const float* __restrict__ gw2, const float* __restrict__ gb2,
                             const float* __restrict__ tw1, const float* __restrict__ tb1,
                             const float* __restrict__ tw2, const float* __restrict__ tb2) {
    int b = blockIdx.x, tid = threadIdx.x;
    if (b < 32) {
#pragma unroll
        for (int t = 0; t < 4; t++) g_adj[b * 1024 + tid + 256 * t] = 0u;
        int i = b * 256 + tid;
        float dist = (float)i * (TBL_MAX / (float)(TBL_N - 1));
        float a[8];
#pragma unroll
        for (int h = 0; h < 8; h++) a[h] = gb2[h];
        for (int c = 0; c < 32; c++) {
            float hv = fmaf(dist, gw1[c], gb1[c]);
            float s = __fdividef(hv, 1.f + __expf(-hv));
#pragma unroll
            for (int h = 0; h < 8; h++) a[h] = fmaf(s, gw2[c * 8 + h], a[h]);
        }
#pragma unroll
        for (int h = 0; h < 8; h++) g_tbl[i * 8 + h] = a[h];
    } else {
        if (tid < 16) {
            float pv = (float)(tid >> 3);
            int h = tid & 7;
            float acc = tb2[h];
            for (int c = 0; c < 32; c++) {
                float hv = fmaf(pv, tw1[c], tb1[c]);
                float s = __fdividef(hv, 1.f + __expf(-hv));
                acc = fmaf(s, tw2[c * 8 + h], acc);
            }
            g_ttab[tid] = acc;
        }
    }
}

// ---------------- scatter edges with inline dtype detect ----------------------
__global__ void scatter_edges_kernel(const unsigned* __restrict__ w) {
    bool is64 = true;
#pragma unroll
    for (int i = 1; i < 16; i += 2) is64 &= (w[i] == 0u);
    int e = blockIdx.x * blockDim.x + threadIdx.x;
    if (e >= NE) return;
    int s, d;
    if (is64) {
        const long long* p = (const long long*)w;
        s = (int)p[e];
        d = (int)p[NE + e];
    } else {
        const int* p = (const int*)w;
        s = p[e];
        d = p[NE + e];
    }
    atomicOr(&g_adj[s * 32 + (d >> 5)], 1u << (d & 31));
}

// path = min(path, path @ adj): binary reachability step on bitsets.
#define LIST_CAP 512
__global__ __launch_bounds__(256) void path_round_kernel(int r) {
    const unsigned* in = (r == 0) ? g_adj : ((r == 1) ? g_pa : g_pb);
    unsigned* out = (r == 1) ? g_pb : g_pa;
    __shared__ unsigned short lists[8][LIST_CAP];
    int warp = threadIdx.x >> 5, lane = threadIdx.x & 31;
    int row = blockIdx.x * 8 + warp;
    unsigned w = in[row * 32 + lane];
    int c = __popc(w);
    int pre = c;
#pragma unroll
    for (int o = 1; o < 32; o <<= 1) {
        int x = __shfl_up_sync(~0u, pre, o);
        if (lane >= o) pre += x;
    }
    int total = __shfl_sync(~0u, pre, 31);
    unsigned acc = 0u;
    if (total <= LIST_CAP) {
        int k = pre - c;
        unsigned tmp = w;
        while (tmp) {
            int b = __ffs(tmp) - 1; tmp &= tmp - 1;
            lists[warp][k++] = (unsigned short)(lane * 32 + b);
        }
        __syncwarp();
        int j = 0;
        for (; j + 8 <= total; j += 8) {
            unsigned a0 = g_adj[lists[warp][j + 0] * 32 + lane];
            unsigned a1 = g_adj[lists[warp][j + 1] * 32 + lane];
            unsigned a2 = g_adj[lists[warp][j + 2] * 32 + lane];
            unsigned a3 = g_adj[lists[warp][j + 3] * 32 + lane];
            unsigned a4 = g_adj[lists[warp][j + 4] * 32 + lane];
            unsigned a5 = g_adj[lists[warp][j + 5] * 32 + lane];
            unsigned a6 = g_adj[lists[warp][j + 6] * 32 + lane];
            unsigned a7 = g_adj[lists[warp][j + 7] * 32 + lane];
            acc |= (a0 | a1) | (a2 | a3) | (a4 | a5) | (a6 | a7);
        }
        for (; j < total; j++) acc |= g_adj[lists[warp][j] * 32 + lane];
    } else {
        for (int ww = 0; ww < 32; ww++) {
            unsigned word = __shfl_sync(~0u, w, ww);
            while (word) {
                int b = __ffs(word) - 1; word &= word - 1;
                acc |= g_adj[(ww * 32 + b) * 32 + lane];
            }
        }
    }
    out[row * 32 + lane] = w & acc;
}

// ---- 64x64 tiled SGEMM body, DOUBLE-BUFFERED, C = [A0|A1]@B + bias [,silu] --
__device__ __forceinline__ void gemm_body(
    const float* __restrict__ A0, const float* __restrict__ A1, int ksplit,
    int lda, const float* __restrict__ B, int ldb,
    const float* __restrict__ bias, float* __restrict__ C, int ldc, int K, int act)
{
    __shared__ float As[2][16][68];
    __shared__ float Bs[2][16][64];
    int tid = threadIdx.x;
    int tx = tid & 15, ty = tid >> 4;
    int row0 = blockIdx.y * 64, col0 = blockIdx.x * 64;
    float acc[4][4];
#pragma unroll
    for (int i = 0; i < 4; i++)
#pragma unroll
        for (int j = 0; j < 4; j++) acc[i][j] = 0.f;
    int ar = tid >> 2, ac = (tid & 3) << 2;
    int bk = tid >> 4, bn = (tid & 15) << 2;

    // prologue: load k-tile 0 into buffer 0
    {
        const float* Ap = (0 < ksplit)
            ? &A0[(row0 + ar) * lda + ac]
            : &A1[(row0 + ar) * lda + ac];
        float4 av = *(const float4*)Ap;
        As[0][ac + 0][ar] = av.x; As[0][ac + 1][ar] = av.y;
        As[0][ac + 2][ar] = av.z; As[0][ac + 3][ar] = av.w;
        *(float4*)&Bs[0][bk][bn] = *(const float4*)&B[bk * ldb + col0 + bn];
    }
    __syncthreads();

    int cur = 0;
    for (int k0 = 0; k0 < K; k0 += 16) {
        int nxt = cur ^ 1;
        bool has_next = (k0 + 16 < K);
        float4 av, bv;
        if (has_next) {
            int k1 = k0 + 16;
            const float* Ap = (k1 < ksplit)
                ? &A0[(row0 + ar) * lda + k1 + ac]
                : &A1[(row0 + ar) * lda + (k1 - ksplit) + ac];
            av = *(const float4*)Ap;
            bv = *(const float4*)&B[(k1 + bk) * ldb + col0 + bn];
        }
#pragma unroll
        for (int kk = 0; kk < 16; kk++) {
            float4 a = *(const float4*)&As[cur][kk][ty << 2];
            float4 b = *(const float4*)&Bs[cur][kk][tx << 2];
            acc[0][0] = fmaf(a.x, b.x, acc[0][0]); acc[0][1] = fmaf(a.x, b.y, acc[0][1]);
            acc[0][2] = fmaf(a.x, b.z, acc[0][2]); acc[0][3] = fmaf(a.x, b.w, acc[0][3]);
            acc[1][0] = fmaf(a.y, b.x, acc[1][0]); acc[1][1] = fmaf(a.y, b.y, acc[1][1]);
            acc[1][2] = fmaf(a.y, b.z, acc[1][2]); acc[1][3] = fmaf(a.y, b.w, acc[1][3]);
            acc[2][0] = fmaf(a.z, b.x, acc[2][0]); acc[2][1] = fmaf(a.z, b.y, acc[2][1]);
            acc[2][2] = fmaf(a.z, b.z, acc[2][2]); acc[2][3] = fmaf(a.z, b.w, acc[2][3]);
            acc[3][0] = fmaf(a.w, b.x, acc[3][0]); acc[3][1] = fmaf(a.w, b.y, acc[3][1]);
            acc[3][2] = fmaf(a.w, b.z, acc[3][2]); acc[3][3] = fmaf(a.w, b.w, acc[3][3]);
        }
        if (has_next) {
            As[nxt][ac + 0][ar] = av.x; As[nxt][ac + 1][ar] = av.y;
            As[nxt][ac + 2][ar] = av.z; As[nxt][ac + 3][ar] = av.w;
            *(float4*)&Bs[nxt][bk][bn] = bv;
            __syncthreads();
        }
        cur = nxt;
    }
#pragma unroll
    for (int i = 0; i < 4; i++) {
        int r = row0 + (ty << 2) + i;
#pragma unroll
        for (int j = 0; j < 4; j++) {
            int cc = col0 + (tx << 2) + j;
            float v = acc[i][j] + bias[cc];
            if (act) v = __fdividef(v, 1.f + __expf(-v));
            C[r * ldc + cc] = v;
        }
    }
}

__global__ __launch_bounds__(256) void sgemm64(
    const float* __restrict__ A0, const float* __restrict__ A1, int ksplit,
    int lda, const float* __restrict__ B, int ldb,
    const float* __restrict__ bias, float* __restrict__ C, int ldc, int K, int act)
{
    gemm_body(A0, A1, ksplit, lda, B, ldb, bias, C, ldc, K, act);
}

// q/k/v projections fused via blockIdx.z
__global__ __launch_bounds__(256) void qkv_kernel(
    const float* __restrict__ src, const float* __restrict__ tgt,
    const float* __restrict__ Wq, const float* __restrict__ bq,
    const float* __restrict__ Wk, const float* __restrict__ bk,
    const float* __restrict__ Wv, const float* __restrict__ bv)
{
    int z = blockIdx.z;
    const float* A = (z == 0) ? src : tgt;
    const float* W = (z == 0) ? Wq : ((z == 1) ? Wk : Wv);
    const float* b = (z == 0) ? bq : ((z == 1) ? bk : bv);
    float* C = (z == 0) ? g_q : ((z == 1) ? g_k : g_v);
    gemm_body(A, A, 256, 256, W, 256, b, C, 256, 256, 0);
}

// gate logits: 2 dots of length 1024 per node, then 2-way softmax
__global__ __launch_bounds__(256) void gate2_kernel(const float* __restrict__ w2,
                                                    const float* __restrict__ b2) {
    int n = blockIdx.x, tid = threadIdx.x;
    const float* hrow = g_gateh + n * 1024;
    float s0 = 0.f, s1 = 0.f;
#pragma unroll
    for (int t = 0; t < 4; t++) {
        int j = tid + 256 * t;
        float hv = hrow[j];
        s0 = fmaf(hv, w2[j * 2 + 0], s0);
        s1 = fmaf(hv, w2[j * 2 + 1], s1);
    }
    for (int o = 16; o; o >>= 1) {
        s0 += __shfl_xor_sync(~0u, s0, o);
        s1 += __shfl_xor_sync(~0u, s1, o);
    }
    __shared__ float r0[8], r1[8];
    if ((tid & 31) == 0) { r0[tid >> 5] = s0; r1[tid >> 5] = s1; }
    __syncthreads();
    if (tid == 0) {
        float l0 = b2[0], l1 = b2[1];
        for (int j = 0; j < 8; j++) { l0 += r0[j]; l1 += r1[j]; }
        float m = fmaxf(l0, l1);
        float e0 = __expf(l0 - m), e1 = __expf(l1 - m);
        float inv = __fdividef(1.f, e0 + e1);
        g_gate[n * 2 + 0] = e0 * inv;
        g_gate[n * 2 + 1] = e1 * inv;
    }
}

// ======== logits: 64n x 32m tile, thread = 4n x 2m x 4h, 2 head-groups =======
#define LQ_QS   0                       // [64][132]
#define LQ_KS   8448                    // [32][132]
#define LQ_SPN  12672                   // 192
#define LQ_SPM  12864                   // 96
#define LQ_SG0  12960                   // 64
#define LQ_SG1  13024                   // 64
#define LQ_STT  13088                   // 16
#define LQ_SPW  13104                   // 64 (unsigned)
#define LOGITS_SMEM ((13104 + 64) * 4)

__global__ __launch_bounds__(256) void logits_kernel(const float* __restrict__ pos)
{
    extern __shared__ float sh[];
    float* qs = sh + LQ_QS;
    float* ks = sh + LQ_KS;
    float* spn = sh + LQ_SPN;
    float* spm = sh + LQ_SPM;
    float* sg0 = sh + LQ_SG0;
    float* sg1 = sh + LQ_SG1;
    float* stt = sh + LQ_STT;
    unsigned* spw = (unsigned*)(sh + LQ_SPW);

    int tid = threadIdx.x;
    int tx = tid & 15, ty = tid >> 4;
    int m0 = blockIdx.x * 32, n0 = blockIdx.y * 64;
    const float scale = 0.17677669529663687f;   // 1/sqrt(32)

    if (tid < 192) spn[tid] = pos[n0 * 3 + tid];
    if (tid < 96)  spm[tid] = pos[m0 * 3 + tid];
    if (tid < 64) {
        sg0[tid] = g_gate[(n0 + tid) * 2 + 0];
        sg1[tid] = g_gate[(n0 + tid) * 2 + 1];
        spw[tid] = g_pa[(n0 + tid) * 32 + (m0 >> 5)];
    }
    if (tid < 16) stt[tid] = g_ttab[tid];
    __syncthreads();

    int i0r[8]; float frr[8]; unsigned bitm = 0;
#pragma unroll
    for (int i = 0; i < 4; i++) {
        int n = ty * 4 + i;
        float pnx = spn[n * 3 + 0], pny = spn[n * 3 + 1], pnz = spn[n * 3 + 2];
#pragma unroll
        for (int j = 0; j < 2; j++) {
            int m = tx + 16 * j;
            float dx = pnx - spm[m * 3 + 0];
            float dy = pny - spm[m * 3 + 1];
            float dz = pnz - spm[m * 3 + 2];
            float dist = sqrtf(fmaxf(dx * dx + dy * dy + dz * dz, 1e-12f));
            float t = fminf(dist, TBL_MAX) * TBL_SCALE;
            int i0 = (int)t;
            if (i0 > TBL_N - 2) i0 = TBL_N - 2;
            int p = i * 2 + j;
            i0r[p] = i0;
            frr[p] = t - (float)i0;
            bitm |= ((spw[n] >> m) & 1u) << p;
        }
    }

    for (int g = 0; g < 2; g++) {
        __syncthreads();
        for (int l = tid; l < 2048; l += 256) {
            int r = l >> 5, c4 = (l & 31) << 2;
            *(float4*)&qs[r * 132 + c4] =
                *(const float4*)&g_q[(n0 + r) * 256 + g * 128 + c4];
        }
        for (int l = tid; l < 1024; l += 256) {
            int r = l >> 5, c4 = (l & 31) << 2;
            *(float4*)&ks[r * 132 + c4] =
                *(const float4*)&g_k[(m0 + r) * 256 + g * 128 + c4];
        }
        __syncthreads();

        float res[4][4][2];
#pragma unroll
        for (int hh = 0; hh < 4; hh++)
#pragma unroll
            for (int i = 0; i < 4; i++) { res[hh][i][0] = 0.f; res[hh][i][1] = 0.f; }

#pragma unroll
        for (int dd = 0; dd < 128; dd += 4) {
            const int hh = dd >> 5;
            float4 qv[4], kv[2];
#pragma unroll
            for (int i = 0; i < 4; i++)
                qv[i] = *(const float4*)&qs[(ty * 4 + i) * 132 + dd];
            kv[0] = *(const float4*)&ks[tx * 132 + dd];
            kv[1] = *(const float4*)&ks[(tx + 16) * 132 + dd];
#pragma unroll
            for (int i = 0; i < 4; i++) {
#pragma unroll
                for (int j = 0; j < 2; j++) {
                    res[hh][i][j] = fmaf(qv[i].x, kv[j].x,
                                    fmaf(qv[i].y, kv[j].y,
                                    fmaf(qv[i].z, kv[j].z,
                                    fmaf(qv[i].w, kv[j].w, res[hh][i][j]))));
                }
            }
        }

        float tt0[4], tt1[4];
#pragma unroll
        for (int hh = 0; hh < 4; hh++) {
            tt0[hh] = stt[4 * g + hh];
            tt1[hh] = stt[8 + 4 * g + hh];
        }
#pragma unroll
        for (int i = 0; i < 4; i++) {
            int n = ty * 4 + i;
            float g0v = sg0[n], g1v = sg1[n];
#pragma unroll
            for (int j = 0; j < 2; j++) {
                int p = i * 2 + j, m = tx + 16 * j;
                int i0 = i0r[p]; float fr = frr[p];
                float4 ta = __ldg((const float4*)&g_tbl[i0 * 8 + 4 * g]);
                float4 tb = __ldg((const float4*)&g_tbl[(i0 + 1) * 8 + 4 * g]);
                float geo[4];
                geo[0] = ta.x + fr * (tb.x - ta.x);
                geo[1] = ta.y + fr * (tb.y - ta.y);
                geo[2] = ta.z + fr * (tb.z - ta.z);
                geo[3] = ta.w + fr * (tb.w - ta.w);
                int bit = (bitm >> p) & 1;
                int base = ((n0 + n) * 8 + 4 * g) * 1024 + m0 + m;
#pragma unroll
                for (int hh = 0; hh < 4; hh++) {
                    float bias = g0v * geo[hh] + g1v * (bit ? tt1[hh] : tt0[hh]);
                    g_logits[base + hh * 1024] = fmaf(res[hh][i][j], scale, bias);
                }
            }
        }
    }
}

// ---------------- row stats (max, 1/sum of exp) -------------------------------
__global__ __launch_bounds__(256) void stats_kernel() {
    int row = blockIdx.x;
    const float* p = g_logits + (long)row * 1024;
    int tid = threadIdx.x;
    float4 v = *(const float4*)&p[tid * 4];
    float mx = fmaxf(fmaxf(v.x, v.y), fmaxf(v.z, v.w));
    for (int o = 16; o; o >>= 1) mx = fmaxf(mx, __shfl_xor_sync(~0u, mx, o));
    __shared__ float rm[8], rs[8];
    if ((tid & 31) == 0) rm[tid >> 5] = mx;
    __syncthreads();
    mx = rm[0];
#pragma unroll
    for (int j = 1; j < 8; j++) mx = fmaxf(mx, rm[j]);
    float s = __expf(v.x - mx) + __expf(v.y - mx) + __expf(v.z - mx) + __expf(v.w - mx);
    for (int o = 16; o; o >>= 1) s += __shfl_xor_sync(~0u, s, o);
    if ((tid & 31) == 0) rs[tid >> 5] = s;
    __syncthreads();
    if (tid == 0) {
        float tot = 0.f;
#pragma unroll
        for (int j = 0; j < 8; j++) tot += rs[j];
        g_stats[row] = make_float2(mx, __fdividef(1.f, tot));
    }
}

// -------- PV with inline softmax, 32-row blocks (256-block grid) -------------
__global__ __launch_bounds__(256) void pv_kernel() {
    int h = blockIdx.x, n0 = blockIdx.y * 32;
    __shared__ float As[32][36];   // n x m (softmaxed probs)
    __shared__ float Bs[32][32];   // m x d
    __shared__ float2 sstat[32];
    int tid = threadIdx.x;
    int dxi = tid & 31;
    int ty = tid >> 5;
    if (tid < 32) sstat[tid] = g_stats[(n0 + tid) * 8 + h];
    __syncthreads();
    float acc[4];
#pragma unroll
    for (int i = 0; i < 4; i++) acc[i] = 0.f;

    for (int m0 = 0; m0 < 1024; m0 += 32) {
        {
            int r = tid >> 3, c4 = (tid & 7) << 2;
            float4 v = *(const float4*)&g_logits[((long)(n0 + r) * 8 + h) * 1024 + m0 + c4];
            float2 st = sstat[r];
            v.x = __expf(v.x - st.x) * st.y;
            v.y = __expf(v.y - st.x) * st.y;
            v.z = __expf(v.z - st.x) * st.y;
            v.w = __expf(v.w - st.x) * st.y;
            *(float4*)&As[r][c4] = v;
            *(float4*)&Bs[r][c4] = *(const float4*)&g_v[(m0 + r) * 256 + h * 32 + c4];
        }
        __syncthreads();
#pragma unroll
        for (int mm = 0; mm < 32; mm += 4) {
            float b0 = Bs[mm + 0][dxi], b1 = Bs[mm + 1][dxi];
            float b2 = Bs[mm + 2][dxi], b3 = Bs[mm + 3][dxi];
#pragma unroll
            for (int i = 0; i < 4; i++) {
                float4 a = *(const float4*)&As[ty + 8 * i][mm];
                acc[i] = fmaf(a.x, b0, fmaf(a.y, b1, fmaf(a.z, b2, fmaf(a.w, b3, acc[i]))));
            }
        }
        __syncthreads();
    }
#pragma unroll
    for (int i = 0; i < 4; i++)
        g_attnout[(n0 + ty + 8 * i) * 256 + h * 32 + dxi] = acc[i];
}

// ---------------- residual + layernorm ----------------------------------------
__global__ __launch_bounds__(256) void ln_kernel(const float* __restrict__ src,
                                                 const float* __restrict__ g,
                                                 const float* __restrict__ b,
                                                 float* __restrict__ out) {
    int n = blockIdx.x, tid = threadIdx.x;
    float x = src[n * 256 + tid] + g_proj[n * 256 + tid];
    float s = x;
    for (int o = 16; o; o >>= 1) s += __shfl_xor_sync(~0u, s, o);
    __shared__ float r1[8], r2[8];
    if ((tid & 31) == 0) r1[tid >> 5] = s;
    __syncthreads();
    float tot = 0.f;
#pragma unroll
    for (int j = 0; j < 8; j++) tot += r1[j];
    float mu = tot * (1.f / 256.f);
    float d = x - mu;
    float s2 = d * d;
    for (int o = 16; o; o >>= 1) s2 += __shfl_xor_sync(~0u, s2, o);
    if ((tid & 31) == 0) r2[tid >> 5] = s2;
    __syncthreads();
    float var = 0.f;
#pragma unroll
    for (int j = 0; j < 8; j++) var += r2[j];
    var *= (1.f / 256.f);
    out[n * 256 + tid] = d * rsqrtf(var + 1e-5f) * g[tid] + b[tid];
}

// ---------------- launch ------------------------------------------------------
extern "C" void kernel_launch(void* const* d_in, const int* in_sizes, int n_in,
                              void* d_out, int out_size) {
    const float* src_feat = (const float*)d_in[0];
    const float* tgt_feat = (const float*)d_in[1];
    const float* src_pos  = (const float*)d_in[2];
    const void*  edges    = d_in[3];
    const float* Wq = (const float*)d_in[4],  *bq = (const float*)d_in[5];
    const float* Wk = (const float*)d_in[6],  *bk = (const float*)d_in[7];
    const float* Wv = (const float*)d_in[8],  *bv = (const float*)d_in[9];
    const float* geo_w1 = (const float*)d_in[10], *geo_b1 = (const float*)d_in[11];
    const float* geo_w2 = (const float*)d_in[12], *geo_b2 = (const float*)d_in[13];
    const float* top_w1 = (const float*)d_in[14], *top_b1 = (const float*)d_in[15];
    const float* top_w2 = (const float*)d_in[16], *top_b2 = (const float*)d_in[17];
    const float* gate_w1 = (const float*)d_in[18], *gate_b1 = (const float*)d_in[19];
    const float* gate_w2 = (const float*)d_in[20], *gate_b2 = (const float*)d_in[21];
    const float* Wo = (const float*)d_in[22], *bo = (const float*)d_in[23];
    const float* ln_g = (const float*)d_in[24], *ln_b = (const float*)d_in[25];
    float* out = (float*)d_out;

    void *pgateh, *pattn, *pproj;
    cudaGetSymbolAddress(&pgateh, g_gateh);
    cudaGetSymbolAddress(&pattn, g_attnout);
    cudaGetSymbolAddress(&pproj, g_proj);

    cudaFuncSetAttribute(logits_kernel,
                         cudaFuncAttributeMaxDynamicSharedMemorySize, LOGITS_SMEM);

    // 1: geo table + zero adj + ttab (fused setup)
    setup_kernel<<<33, 256>>>(geo_w1, geo_b1, geo_w2, geo_b2,
                              top_w1, top_b1, top_w2, top_b2);
    // 2: scatter edges (inline dtype detect)
    scatter_edges_kernel<<<64, 256>>>((const unsigned*)edges);
    // 3: path round 1
    path_round_kernel<<<128, 256>>>(0);
    // 4: gate MLP GEMM (positioned for ncu capture): 1024x1024, K=512, 256 blocks
    sgemm64<<<dim3(16, 16), 256>>>(src_feat, tgt_feat, 256, 256, gate_w1, 1024,
                                   gate_b1, (float*)pgateh, 1024, 512, 1);
    // 5-6: path rounds 2,3 (final path in g_pa)
    path_round_kernel<<<128, 256>>>(1);
    path_round_kernel<<<128, 256>>>(2);
    // 7: q/k/v projections (192 blocks)
    qkv_kernel<<<dim3(4, 16, 3), 256>>>(src_feat, tgt_feat, Wq, bq, Wk, bk, Wv, bv);
    // 8: gate head + 2-way softmax
    gate2_kernel<<<1024, 256>>>(gate_w2, gate_b2);
    // 9-11: fused logits (512 blocks), row stats, PV (256 blocks)
    logits_kernel<<<dim3(32, 16), 256, LOGITS_SMEM>>>(src_pos);
    stats_kernel<<<8192, 256>>>();
    pv_kernel<<<dim3(8, 32), 256>>>();
    // 12: output projection
    sgemm64<<<dim3(4, 16), 256>>>((const float*)pattn, (const float*)pattn, 256, 256,
                                  Wo, 256, bo, (float*)pproj, 256, 256, 0);
    // 13: residual + layernorm
    ln_kernel<<<1024, 256>>>(src_feat, ln_g, ln_b, out);
}